// round 10
// baseline (speedup 1.0000x reference)
#include <cuda_runtime.h>
#include <math.h>

// Problem constants (fixed by the dataset)
#define B_ 4
#define S_ 256
#define E_ 256
#define H_ 128
#define N_ (B_ * S_)   // 1024 rows total

// Scratch (static device arrays; allocation-free per harness rules)
__device__ float g_ampq2[2][N_ * E_];   // split-K partials
__device__ float g_ampk2[2][N_ * E_];
__device__ float g_V2[2][N_ * H_];
__device__ float g_V[N_ * H_];
__device__ float g_Pq[N_ * E_];   // row-major, query side
__device__ float g_Pk[N_ * E_];   // row-major, key side
__device__ float g_entq[N_];      // sum_e P * lg2(P + 1e-10)
__device__ float g_entk[N_];
__device__ float g_score[N_ * S_];   // masked (pre-normalization) scores

// ---------------------------------------------------------------------------
// Kernel 1 (unchanged, proven R9): split-K double-buffered GEMM.
// C[1024, 640] = x[1024,256] @ [Wq;Wk;Wv]^T.  64x64 CTA tile, 256 thr,
// 4x4 micro, 16 FFMA per 2 LDS.128, z = K-half; 2-deep smem buffers with
// register prefetch.  Grid 16x10x2 = 320 CTAs.
// ---------------------------------------------------------------------------
__global__ __launch_bounds__(256) void k1_gemm(
    const float* __restrict__ x,
    const float* __restrict__ Wq,
    const float* __restrict__ Wk,
    const float* __restrict__ Wv)
{
    __shared__ float As[2][32][68];  // [buf][k][m], pad keeps float4 alignment
    __shared__ float Bs[2][32][68];  // [buf][k][f]

    const int m0 = blockIdx.x * 64;       // row tile (0..15)
    const int f0 = blockIdx.y * 64;       // f tile (0..9) over concat 640
    const int z  = blockIdx.z;            // K half
    const int kbase = z * 128;

    const float* Wp; float* outp; int fo, ostride;
    if (f0 < 256)      { Wp = Wq; fo = f0;       outp = g_ampq2[z]; ostride = E_; }
    else if (f0 < 512) { Wp = Wk; fo = f0 - 256; outp = g_ampk2[z]; ostride = E_; }
    else               { Wp = Wv; fo = f0 - 512; outp = g_V2[z];    ostride = H_; }

    const int tid  = threadIdx.x;
    const int tx   = tid & 15;            // f micro
    const int ty   = tid >> 4;            // m micro
    const int lrow = tid >> 2;            // 0..63 loader row
    const int lk   = (tid & 3) * 8;       // 0,8,16,24 loader k base

    const float* xg = x  + (m0 + lrow) * E_ + kbase + lk;
    const float* wg = Wp + (fo + lrow) * E_ + kbase + lk;

    float acc[4][4] = {};

    float4 a0 = *(const float4*)(xg);
    float4 a1 = *(const float4*)(xg + 4);
    float4 b0 = *(const float4*)(wg);
    float4 b1 = *(const float4*)(wg + 4);
    {
        As[0][lk+0][lrow] = a0.x; As[0][lk+1][lrow] = a0.y;
        As[0][lk+2][lrow] = a0.z; As[0][lk+3][lrow] = a0.w;
        As[0][lk+4][lrow] = a1.x; As[0][lk+5][lrow] = a1.y;
        As[0][lk+6][lrow] = a1.z; As[0][lk+7][lrow] = a1.w;
        Bs[0][lk+0][lrow] = b0.x; Bs[0][lk+1][lrow] = b0.y;
        Bs[0][lk+2][lrow] = b0.z; Bs[0][lk+3][lrow] = b0.w;
        Bs[0][lk+4][lrow] = b1.x; Bs[0][lk+5][lrow] = b1.y;
        Bs[0][lk+6][lrow] = b1.z; Bs[0][lk+7][lrow] = b1.w;
    }
    __syncthreads();

    #pragma unroll
    for (int c = 0; c < 4; c++) {
        const int buf = c & 1;
        if (c < 3) {                      // prefetch next chunk BEFORE compute
            const int k0 = (c + 1) * 32;
            a0 = *(const float4*)(xg + k0);
            a1 = *(const float4*)(xg + k0 + 4);
            b0 = *(const float4*)(wg + k0);
            b1 = *(const float4*)(wg + k0 + 4);
        }

        #pragma unroll
        for (int kk = 0; kk < 32; kk++) {
            float4 av = *(const float4*)&As[buf][kk][ty * 4];
            float4 bv = *(const float4*)&Bs[buf][kk][tx * 4];
            acc[0][0] = fmaf(av.x, bv.x, acc[0][0]);
            acc[0][1] = fmaf(av.x, bv.y, acc[0][1]);
            acc[0][2] = fmaf(av.x, bv.z, acc[0][2]);
            acc[0][3] = fmaf(av.x, bv.w, acc[0][3]);
            acc[1][0] = fmaf(av.y, bv.x, acc[1][0]);
            acc[1][1] = fmaf(av.y, bv.y, acc[1][1]);
            acc[1][2] = fmaf(av.y, bv.z, acc[1][2]);
            acc[1][3] = fmaf(av.y, bv.w, acc[1][3]);
            acc[2][0] = fmaf(av.z, bv.x, acc[2][0]);
            acc[2][1] = fmaf(av.z, bv.y, acc[2][1]);
            acc[2][2] = fmaf(av.z, bv.z, acc[2][2]);
            acc[2][3] = fmaf(av.z, bv.w, acc[2][3]);
            acc[3][0] = fmaf(av.w, bv.x, acc[3][0]);
            acc[3][1] = fmaf(av.w, bv.y, acc[3][1]);
            acc[3][2] = fmaf(av.w, bv.z, acc[3][2]);
            acc[3][3] = fmaf(av.w, bv.w, acc[3][3]);
        }

        if (c < 3) {                      // stage next chunk into other buffer
            const int nb = buf ^ 1;
            As[nb][lk+0][lrow] = a0.x; As[nb][lk+1][lrow] = a0.y;
            As[nb][lk+2][lrow] = a0.z; As[nb][lk+3][lrow] = a0.w;
            As[nb][lk+4][lrow] = a1.x; As[nb][lk+5][lrow] = a1.y;
            As[nb][lk+6][lrow] = a1.z; As[nb][lk+7][lrow] = a1.w;
            Bs[nb][lk+0][lrow] = b0.x; Bs[nb][lk+1][lrow] = b0.y;
            Bs[nb][lk+2][lrow] = b0.z; Bs[nb][lk+3][lrow] = b0.w;
            Bs[nb][lk+4][lrow] = b1.x; Bs[nb][lk+5][lrow] = b1.y;
            Bs[nb][lk+6][lrow] = b1.z; Bs[nb][lk+7][lrow] = b1.w;
            __syncthreads();
        }
    }

    #pragma unroll
    for (int i = 0; i < 4; i++) {
        const int row = m0 + ty * 4 + i;
        float4 v = make_float4(acc[i][0], acc[i][1], acc[i][2], acc[i][3]);
        *(float4*)&outp[row * ostride + fo + tx * 4] = v;
    }
}

// ---------------------------------------------------------------------------
// Kernel 2 (unchanged, proven): warp-per-row split-K combine + probs +
// entropy.  Regions 0/1 (q/k): amp = part0+part1, P = amp^2/(ssq+EPS*d^2),
// ent = sum P*lg2(P+EPS).  Region 2: V = V0+V1.  grid 384 x 256.
// ---------------------------------------------------------------------------
__global__ __launch_bounds__(256) void k2_probs(const float* __restrict__ x)
{
    const int w    = threadIdx.x >> 5;
    const int lane = threadIdx.x & 31;
    const int slot = blockIdx.x * 8 + w;       // 0..3071
    const int regn = slot >> 10;               // 0 = q, 1 = k, 2 = V-combine
    const int n    = slot & 1023;

    if (regn == 2) {
        const float4* v0 = (const float4*)&g_V2[0][n * H_];
        const float4* v1 = (const float4*)&g_V2[1][n * H_];
        float4*       vo = (float4*)&g_V[n * H_];
        const float4 a = v0[lane], b = v1[lane];
        vo[lane] = make_float4(a.x + b.x, a.y + b.y, a.z + b.z, a.w + b.w);
        return;
    }

    const float* a0 = (regn ? g_ampk2[0] : g_ampq2[0]) + n * E_;
    const float* a1 = (regn ? g_ampk2[1] : g_ampq2[1]) + n * E_;
    float*     Pout = (regn ? g_Pk       : g_Pq)       + n * E_;
    const float* xr = x + n * E_;

    float a[8];
    float ssa = 0.f, ssx = 0.f;
    #pragma unroll
    for (int m = 0; m < 8; m++) {
        a[m] = a0[lane + 32 * m] + a1[lane + 32 * m];
        float xv = xr[lane + 32 * m];
        ssa = fmaf(a[m], a[m], ssa);
        ssx = fmaf(xv, xv, ssx);
    }
    #pragma unroll
    for (int o = 16; o; o >>= 1) {
        ssa += __shfl_xor_sync(0xffffffffu, ssa, o);
        ssx += __shfl_xor_sync(0xffffffffu, ssx, o);
    }
    const float d   = sqrtf(ssx) + 1e-12f;
    const float inv = 1.0f / (ssa + 1e-10f * d * d);

    float ent = 0.f;
    #pragma unroll
    for (int m = 0; m < 8; m++) {
        const float P = a[m] * a[m] * inv;
        ent = fmaf(P, __log2f(P + 1e-10f), ent);
        Pout[lane + 32 * m] = P;
    }
    #pragma unroll
    for (int o = 16; o; o >>= 1)
        ent += __shfl_xor_sync(0xffffffffu, ent, o);
    if (lane == 0) (regn ? g_entk : g_entq)[n] = ent;
}

// ---------------------------------------------------------------------------
// Kernel 3a (unchanged, proven): shuffle-free JS scores.
// CTA = (8-row block, 32-j block, batch); grid (32, 8, 4); fully-masked
// blocks exit.  sPk stride-257 padding -> conflict-free column reads.
// Warp w owns row i0+w, lane owns j0+lane.  MUFU-bound.
// ---------------------------------------------------------------------------
__global__ __launch_bounds__(256) void k3a_score()
{
    const int rb = blockIdx.x;         // row block: rows 8rb..8rb+7
    const int jb = blockIdx.y;         // j block:   js  32jb..32jb+31
    const int b  = blockIdx.z;
    if (jb > (rb >> 2)) return;        // whole block above the diagonal

    __shared__ float sPk[32][257];     // [j_local][e], stride 257
    __shared__ float sP[8][256];       // [row_local][e]
    __shared__ float sHk[32];

    const int tid  = threadIdx.x;
    const int w    = tid >> 5;
    const int lane = tid & 31;
    const int i0 = rb * 8, j0 = jb * 32;

    // Stage Pk rows (warp w -> rows 4w..4w+3; 8 lanes per row, coalesced 128B)
    {
        const int row = 4 * w + (lane >> 3);
        const int fb  = lane & 7;
        const float* src = g_Pk + (b * S_ + j0 + row) * E_;
        #pragma unroll
        for (int it = 0; it < 8; it++) {
            const int f = fb + 8 * it;          // float4 index within row
            float4 v = *(const float4*)(src + 4 * f);
            sPk[row][4*f+0] = v.x; sPk[row][4*f+1] = v.y;
            sPk[row][4*f+2] = v.z; sPk[row][4*f+3] = v.w;
        }
    }
    // Stage Pq rows (warp w -> row w, two float4 per lane, coalesced)
    {
        const float* src = g_Pq + (b * S_ + i0 + w) * E_;
        *(float4*)&sP[w][4 * lane]        = *(const float4*)(src + 4 * lane);
        *(float4*)&sP[w][128 + 4 * lane]  = *(const float4*)(src + 128 + 4 * lane);
    }
    if (tid < 32) sHk[tid] = g_entk[b * S_ + j0 + tid];
    __syncthreads();

    const float hq = g_entq[b * S_ + i0 + w];
    const float hk = sHk[lane];

    float ac0 = 0.f, ac1 = 0.f, ac2 = 0.f, ac3 = 0.f;
    #pragma unroll 8
    for (int e = 0; e < E_; e += 4) {
        const float4 p = *(const float4*)&sP[w][e];
        const float s0 = p.x + sPk[lane][e + 0];
        const float s1 = p.y + sPk[lane][e + 1];
        const float s2 = p.z + sPk[lane][e + 2];
        const float s3 = p.w + sPk[lane][e + 3];
        ac0 = fmaf(s0, __log2f(fmaf(0.5f, s0, 1e-10f)), ac0);
        ac1 = fmaf(s1, __log2f(fmaf(0.5f, s1, 1e-10f)), ac1);
        ac2 = fmaf(s2, __log2f(fmaf(0.5f, s2, 1e-10f)), ac2);
        ac3 = fmaf(s3, __log2f(fmaf(0.5f, s3, 1e-10f)), ac3);
    }
    const float acc = (ac0 + ac1) + (ac2 + ac3);

    const int i = i0 + w, j = j0 + lane;
    const float HL = 0.34657359028f;             // 0.5 * ln(2)
    const float score = 1.0f - HL * (hq + hk - acc);
    g_score[(b * S_ + i) * S_ + j] = (j <= i) ? score : 0.0f;   // coalesced
}

// ---------------------------------------------------------------------------
// Kernel 3b v2: blocked row-normalize + attn @ V.
// One CTA per 8 consecutive query rows (grid 128).  Scores staged (and
// masked -- the region above each diagonal 32-block is never written by k3a)
// into smem; 8 L1 row-sums via one per-warp butterfly; V accumulation with
// thread = (half, h) and 8 register accumulators: per 4 j's the inner step
// is 8 broadcast LDS.128 + 4 coalesced LDG + 32 FMA (vs R9's 1 LDG + 2 FMA
// per j with MLP=1, which made this kernel the 19 us hotspot).
// ---------------------------------------------------------------------------
__global__ __launch_bounds__(256) void k3b_out(float* __restrict__ out)
{
    __shared__ float sScore[8][256];   // 8 KB
    __shared__ float sO[8][128];       // 4 KB
    __shared__ float sInv[8];

    const int c  = blockIdx.x;        // 0..127
    const int n0 = c * 8;
    const int b  = n0 >> 8;
    const int i0 = n0 & 255;          // rows i0..i0+7 (same batch: 8 | 256)
    const int tid  = threadIdx.x;
    const int w    = tid >> 5;
    const int lane = tid & 31;

    // Stage + mask scores: warp w -> row w (j > i_row zeroed; covers both the
    // in-block upper triangle -- already 0 -- and the unwritten region).
    {
        const int i_row = i0 + w;
        const float* src = g_score + (n0 + w) * S_;
        #pragma unroll
        for (int t = 0; t < 2; t++) {
            const int j4 = 4 * lane + 128 * t;
            float4 v = *(const float4*)(src + j4);
            v.x = (j4 + 0 <= i_row) ? v.x : 0.f;
            v.y = (j4 + 1 <= i_row) ? v.y : 0.f;
            v.z = (j4 + 2 <= i_row) ? v.z : 0.f;
            v.w = (j4 + 3 <= i_row) ? v.w : 0.f;
            *(float4*)&sScore[w][j4] = v;
        }
    }

    // L1 row sum for row w (own-warp data; no cross-warp dependency yet).
    float rs = 0.f;
    #pragma unroll
    for (int m = 0; m < 8; m++) rs += fabsf(sScore[w][lane + 32 * m]);
    #pragma unroll
    for (int o = 16; o; o >>= 1) rs += __shfl_xor_sync(0xffffffffu, rs, o);
    if (lane == 0) sInv[w] = 1.0f / fmaxf(rs, 1e-12f);
    __syncthreads();

    // V accumulation: thread = (half = tid>>7, h = tid&127), 8 row accums.
    // j processed in float4 groups: half 0 takes j4 = 0,8,16,..; half 1 takes
    // j4 = 4,12,20,..  jmax = i0+7 (== 7 mod 8) so j4+3 never over-runs.
    const int half = tid >> 7;
    const int h    = tid & 127;
    const float* Vb = g_V + b * S_ * H_;
    float acc[8] = {};
    const int jmax = i0 + 7;
    for (int j4 = 4 * half; j4 <= jmax; j4 += 8) {
        const float v0 = Vb[(j4 + 0) * H_ + h];
        const float v1 = Vb[(j4 + 1) * H_ + h];
        const float v2 = Vb[(j4 + 2) * H_ + h];
        const float v3 = Vb[(j4 + 3) * H_ + h];
        #pragma unroll
        for (int r = 0; r < 8; r++) {
            const float4 s = *(const float4*)&sScore[r][j4];  // warp-broadcast
            acc[r] = fmaf(s.x, v0, acc[r]);
            acc[r] = fmaf(s.y, v1, acc[r]);
            acc[r] = fmaf(s.z, v2, acc[r]);
            acc[r] = fmaf(s.w, v3, acc[r]);
        }
    }
    if (half == 1) {
        #pragma unroll
        for (int r = 0; r < 8; r++) sO[r][h] = acc[r];
    }
    __syncthreads();
    if (half == 0) {
        #pragma unroll
        for (int r = 0; r < 8; r++)
            out[(n0 + r) * H_ + h] = (acc[r] + sO[r][h]) * sInv[r];
    }
}

// ---------------------------------------------------------------------------
// Launch. Inputs per metadata order: x, Wv, Wq, Wk (all float32).
// ---------------------------------------------------------------------------
extern "C" void kernel_launch(void* const* d_in, const int* in_sizes, int n_in,
                              void* d_out, int out_size)
{
    const float* x  = (const float*)d_in[0];
    const float* Wv = (const float*)d_in[1];
    const float* Wq = (const float*)d_in[2];
    const float* Wk = (const float*)d_in[3];
    float* out = (float*)d_out;

    k1_gemm<<<dim3(16, 10, 2), 256>>>(x, Wq, Wk, Wv);
    k2_probs<<<384, 256>>>(x);
    k3a_score<<<dim3(32, 8, 4), 256>>>();
    k3b_out<<<128, 256>>>(out);
}

// round 11
// speedup vs baseline: 1.0434x; 1.0434x over previous
#include <cuda_runtime.h>
#include <math.h>

// Problem constants (fixed by the dataset)
#define B_ 4
#define S_ 256
#define E_ 256
#define H_ 128
#define N_ (B_ * S_)   // 1024 rows total

// Scratch (static device arrays; allocation-free per harness rules)
__device__ float g_ampq2[2][N_ * E_];   // split-K partials
__device__ float g_ampk2[2][N_ * E_];
__device__ float g_V2[2][N_ * H_];
__device__ float g_V[N_ * H_];
__device__ float g_Pq[N_ * E_];   // row-major, query side
__device__ float g_Pk[N_ * E_];   // row-major, key side
__device__ float g_entq[N_];      // sum_e P * lg2(P + 1e-10)
__device__ float g_entk[N_];
__device__ float g_score[N_ * S_];   // masked (pre-normalization) scores

// ---------------------------------------------------------------------------
// Kernel 1 (unchanged, proven): split-K double-buffered GEMM.
// C[1024, 640] = x[1024,256] @ [Wq;Wk;Wv]^T.  64x64 CTA tile, 256 thr,
// 4x4 micro, 16 FFMA per 2 LDS.128, z = K-half; 2-deep smem buffers with
// register prefetch.  Grid 16x10x2 = 320 CTAs.
// ---------------------------------------------------------------------------
__global__ __launch_bounds__(256) void k1_gemm(
    const float* __restrict__ x,
    const float* __restrict__ Wq,
    const float* __restrict__ Wk,
    const float* __restrict__ Wv)
{
    __shared__ float As[2][32][68];  // [buf][k][m], pad keeps float4 alignment
    __shared__ float Bs[2][32][68];  // [buf][k][f]

    const int m0 = blockIdx.x * 64;       // row tile (0..15)
    const int f0 = blockIdx.y * 64;       // f tile (0..9) over concat 640
    const int z  = blockIdx.z;            // K half
    const int kbase = z * 128;

    const float* Wp; float* outp; int fo, ostride;
    if (f0 < 256)      { Wp = Wq; fo = f0;       outp = g_ampq2[z]; ostride = E_; }
    else if (f0 < 512) { Wp = Wk; fo = f0 - 256; outp = g_ampk2[z]; ostride = E_; }
    else               { Wp = Wv; fo = f0 - 512; outp = g_V2[z];    ostride = H_; }

    const int tid  = threadIdx.x;
    const int tx   = tid & 15;            // f micro
    const int ty   = tid >> 4;            // m micro
    const int lrow = tid >> 2;            // 0..63 loader row
    const int lk   = (tid & 3) * 8;       // 0,8,16,24 loader k base

    const float* xg = x  + (m0 + lrow) * E_ + kbase + lk;
    const float* wg = Wp + (fo + lrow) * E_ + kbase + lk;

    float acc[4][4] = {};

    float4 a0 = *(const float4*)(xg);
    float4 a1 = *(const float4*)(xg + 4);
    float4 b0 = *(const float4*)(wg);
    float4 b1 = *(const float4*)(wg + 4);
    {
        As[0][lk+0][lrow] = a0.x; As[0][lk+1][lrow] = a0.y;
        As[0][lk+2][lrow] = a0.z; As[0][lk+3][lrow] = a0.w;
        As[0][lk+4][lrow] = a1.x; As[0][lk+5][lrow] = a1.y;
        As[0][lk+6][lrow] = a1.z; As[0][lk+7][lrow] = a1.w;
        Bs[0][lk+0][lrow] = b0.x; Bs[0][lk+1][lrow] = b0.y;
        Bs[0][lk+2][lrow] = b0.z; Bs[0][lk+3][lrow] = b0.w;
        Bs[0][lk+4][lrow] = b1.x; Bs[0][lk+5][lrow] = b1.y;
        Bs[0][lk+6][lrow] = b1.z; Bs[0][lk+7][lrow] = b1.w;
    }
    __syncthreads();

    #pragma unroll
    for (int c = 0; c < 4; c++) {
        const int buf = c & 1;
        if (c < 3) {                      // prefetch next chunk BEFORE compute
            const int k0 = (c + 1) * 32;
            a0 = *(const float4*)(xg + k0);
            a1 = *(const float4*)(xg + k0 + 4);
            b0 = *(const float4*)(wg + k0);
            b1 = *(const float4*)(wg + k0 + 4);
        }

        #pragma unroll
        for (int kk = 0; kk < 32; kk++) {
            float4 av = *(const float4*)&As[buf][kk][ty * 4];
            float4 bv = *(const float4*)&Bs[buf][kk][tx * 4];
            acc[0][0] = fmaf(av.x, bv.x, acc[0][0]);
            acc[0][1] = fmaf(av.x, bv.y, acc[0][1]);
            acc[0][2] = fmaf(av.x, bv.z, acc[0][2]);
            acc[0][3] = fmaf(av.x, bv.w, acc[0][3]);
            acc[1][0] = fmaf(av.y, bv.x, acc[1][0]);
            acc[1][1] = fmaf(av.y, bv.y, acc[1][1]);
            acc[1][2] = fmaf(av.y, bv.z, acc[1][2]);
            acc[1][3] = fmaf(av.y, bv.w, acc[1][3]);
            acc[2][0] = fmaf(av.z, bv.x, acc[2][0]);
            acc[2][1] = fmaf(av.z, bv.y, acc[2][1]);
            acc[2][2] = fmaf(av.z, bv.z, acc[2][2]);
            acc[2][3] = fmaf(av.z, bv.w, acc[2][3]);
            acc[3][0] = fmaf(av.w, bv.x, acc[3][0]);
            acc[3][1] = fmaf(av.w, bv.y, acc[3][1]);
            acc[3][2] = fmaf(av.w, bv.z, acc[3][2]);
            acc[3][3] = fmaf(av.w, bv.w, acc[3][3]);
        }

        if (c < 3) {                      // stage next chunk into other buffer
            const int nb = buf ^ 1;
            As[nb][lk+0][lrow] = a0.x; As[nb][lk+1][lrow] = a0.y;
            As[nb][lk+2][lrow] = a0.z; As[nb][lk+3][lrow] = a0.w;
            As[nb][lk+4][lrow] = a1.x; As[nb][lk+5][lrow] = a1.y;
            As[nb][lk+6][lrow] = a1.z; As[nb][lk+7][lrow] = a1.w;
            Bs[nb][lk+0][lrow] = b0.x; Bs[nb][lk+1][lrow] = b0.y;
            Bs[nb][lk+2][lrow] = b0.z; Bs[nb][lk+3][lrow] = b0.w;
            Bs[nb][lk+4][lrow] = b1.x; Bs[nb][lk+5][lrow] = b1.y;
            Bs[nb][lk+6][lrow] = b1.z; Bs[nb][lk+7][lrow] = b1.w;
            __syncthreads();
        }
    }

    #pragma unroll
    for (int i = 0; i < 4; i++) {
        const int row = m0 + ty * 4 + i;
        float4 v = make_float4(acc[i][0], acc[i][1], acc[i][2], acc[i][3]);
        *(float4*)&outp[row * ostride + fo + tx * 4] = v;
    }
}

// ---------------------------------------------------------------------------
// Kernel 2 (unchanged, proven): warp-per-row split-K combine + probs +
// entropy.  Regions 0/1 (q/k): amp = part0+part1, P = amp^2/(ssq+EPS*d^2),
// ent = sum P*lg2(P+EPS).  Region 2: V = V0+V1.  grid 384 x 256.
// ---------------------------------------------------------------------------
__global__ __launch_bounds__(256) void k2_probs(const float* __restrict__ x)
{
    const int w    = threadIdx.x >> 5;
    const int lane = threadIdx.x & 31;
    const int slot = blockIdx.x * 8 + w;       // 0..3071
    const int regn = slot >> 10;               // 0 = q, 1 = k, 2 = V-combine
    const int n    = slot & 1023;

    if (regn == 2) {
        const float4* v0 = (const float4*)&g_V2[0][n * H_];
        const float4* v1 = (const float4*)&g_V2[1][n * H_];
        float4*       vo = (float4*)&g_V[n * H_];
        const float4 a = v0[lane], b = v1[lane];
        vo[lane] = make_float4(a.x + b.x, a.y + b.y, a.z + b.z, a.w + b.w);
        return;
    }

    const float* a0 = (regn ? g_ampk2[0] : g_ampq2[0]) + n * E_;
    const float* a1 = (regn ? g_ampk2[1] : g_ampq2[1]) + n * E_;
    float*     Pout = (regn ? g_Pk       : g_Pq)       + n * E_;
    const float* xr = x + n * E_;

    float a[8];
    float ssa = 0.f, ssx = 0.f;
    #pragma unroll
    for (int m = 0; m < 8; m++) {
        a[m] = a0[lane + 32 * m] + a1[lane + 32 * m];
        float xv = xr[lane + 32 * m];
        ssa = fmaf(a[m], a[m], ssa);
        ssx = fmaf(xv, xv, ssx);
    }
    #pragma unroll
    for (int o = 16; o; o >>= 1) {
        ssa += __shfl_xor_sync(0xffffffffu, ssa, o);
        ssx += __shfl_xor_sync(0xffffffffu, ssx, o);
    }
    const float d   = sqrtf(ssx) + 1e-12f;
    const float inv = 1.0f / (ssa + 1e-10f * d * d);

    float ent = 0.f;
    #pragma unroll
    for (int m = 0; m < 8; m++) {
        const float P = a[m] * a[m] * inv;
        ent = fmaf(P, __log2f(P + 1e-10f), ent);
        Pout[lane + 32 * m] = P;
    }
    #pragma unroll
    for (int o = 16; o; o >>= 1)
        ent += __shfl_xor_sync(0xffffffffu, ent, o);
    if (lane == 0) (regn ? g_entk : g_entq)[n] = ent;
}

// ---------------------------------------------------------------------------
// Kernel 3a (unchanged, proven): shuffle-free JS scores.
// CTA = (8-row block, 32-j block, batch); grid (32, 8, 4); fully-masked
// blocks exit.  sPk stride-257 padding -> conflict-free column reads.
// Warp w owns row i0+w, lane owns j0+lane.  MUFU-bound.
// ---------------------------------------------------------------------------
__global__ __launch_bounds__(256) void k3a_score()
{
    const int rb = blockIdx.x;         // row block: rows 8rb..8rb+7
    const int jb = blockIdx.y;         // j block:   js  32jb..32jb+31
    const int b  = blockIdx.z;
    if (jb > (rb >> 2)) return;        // whole block above the diagonal

    __shared__ float sPk[32][257];     // [j_local][e], stride 257
    __shared__ float sP[8][256];       // [row_local][e]
    __shared__ float sHk[32];

    const int tid  = threadIdx.x;
    const int w    = tid >> 5;
    const int lane = tid & 31;
    const int i0 = rb * 8, j0 = jb * 32;

    // Stage Pk rows (warp w -> rows 4w..4w+3; 8 lanes per row, coalesced 128B)
    {
        const int row = 4 * w + (lane >> 3);
        const int fb  = lane & 7;
        const float* src = g_Pk + (b * S_ + j0 + row) * E_;
        #pragma unroll
        for (int it = 0; it < 8; it++) {
            const int f = fb + 8 * it;          // float4 index within row
            float4 v = *(const float4*)(src + 4 * f);
            sPk[row][4*f+0] = v.x; sPk[row][4*f+1] = v.y;
            sPk[row][4*f+2] = v.z; sPk[row][4*f+3] = v.w;
        }
    }
    // Stage Pq rows (warp w -> row w, two float4 per lane, coalesced)
    {
        const float* src = g_Pq + (b * S_ + i0 + w) * E_;
        *(float4*)&sP[w][4 * lane]        = *(const float4*)(src + 4 * lane);
        *(float4*)&sP[w][128 + 4 * lane]  = *(const float4*)(src + 128 + 4 * lane);
    }
    if (tid < 32) sHk[tid] = g_entk[b * S_ + j0 + tid];
    __syncthreads();

    const float hq = g_entq[b * S_ + i0 + w];
    const float hk = sHk[lane];

    float ac0 = 0.f, ac1 = 0.f, ac2 = 0.f, ac3 = 0.f;
    #pragma unroll 8
    for (int e = 0; e < E_; e += 4) {
        const float4 p = *(const float4*)&sP[w][e];
        const float s0 = p.x + sPk[lane][e + 0];
        const float s1 = p.y + sPk[lane][e + 1];
        const float s2 = p.z + sPk[lane][e + 2];
        const float s3 = p.w + sPk[lane][e + 3];
        ac0 = fmaf(s0, __log2f(fmaf(0.5f, s0, 1e-10f)), ac0);
        ac1 = fmaf(s1, __log2f(fmaf(0.5f, s1, 1e-10f)), ac1);
        ac2 = fmaf(s2, __log2f(fmaf(0.5f, s2, 1e-10f)), ac2);
        ac3 = fmaf(s3, __log2f(fmaf(0.5f, s3, 1e-10f)), ac3);
    }
    const float acc = (ac0 + ac1) + (ac2 + ac3);

    const int i = i0 + w, j = j0 + lane;
    const float HL = 0.34657359028f;             // 0.5 * ln(2)
    const float score = 1.0f - HL * (hq + hk - acc);
    g_score[(b * S_ + i) * S_ + j] = (j <= i) ? score : 0.0f;   // coalesced
}

// ---------------------------------------------------------------------------
// Kernel 3b v3: blocked row-normalize + attn @ V with 4-way j-parallelism.
// R10's version was latency-starved (8 warps/SM, 32 serial LDG iterations,
// occ=issue=12.4%).  Now: 512 threads (16 warps/SM) and the j-range split
// across 4 thread-quarters -> per-thread iterations <= 16; partial sums
// combined through smem.  Row L1 sums come from staging REGISTERS (own-lane
// values + butterfly), removing the smem RAW hazard.  Grid 128.
// ---------------------------------------------------------------------------
__global__ __launch_bounds__(512) void k3b_out(float* __restrict__ out)
{
    __shared__ float sScore[8][256];    //  8 KB
    __shared__ float sOp[3][8][128];    // 12 KB partial O from quarters 1..3
    __shared__ float sInv[8];

    const int c  = blockIdx.x;        // 0..127
    const int n0 = c * 8;
    const int b  = n0 >> 8;
    const int i0 = n0 & 255;          // rows i0..i0+7 (same batch: 8 | 256)
    const int tid  = threadIdx.x;
    const int w    = tid >> 5;
    const int lane = tid & 31;

    // Warps 0..7: stage + mask scores for row w, and compute the row L1 sum
    // from the registers just loaded (no smem read-back needed).
    if (w < 8) {
        const int i_row = i0 + w;
        const float* src = g_score + (n0 + w) * S_;
        float rs = 0.f;
        #pragma unroll
        for (int t = 0; t < 2; t++) {
            const int j4 = 4 * lane + 128 * t;
            float4 v = *(const float4*)(src + j4);
            v.x = (j4 + 0 <= i_row) ? v.x : 0.f;
            v.y = (j4 + 1 <= i_row) ? v.y : 0.f;
            v.z = (j4 + 2 <= i_row) ? v.z : 0.f;
            v.w = (j4 + 3 <= i_row) ? v.w : 0.f;
            *(float4*)&sScore[w][j4] = v;
            rs += fabsf(v.x) + fabsf(v.y) + fabsf(v.z) + fabsf(v.w);
        }
        #pragma unroll
        for (int o = 16; o; o >>= 1) rs += __shfl_xor_sync(0xffffffffu, rs, o);
        if (lane == 0) sInv[w] = 1.0f / fmaxf(rs, 1e-12f);
    }
    __syncthreads();

    // V accumulation: thread = (quarter = tid>>7, h = tid&127), 8 row accums.
    // Quarter q takes j4 = 4q, 4q+16, 4q+32, ...  (<= 16 iterations each).
    // jmax = i0+7 == 7 (mod 8), so j4 <= jmax implies j4+3 <= 255: in-bounds,
    // and entries with j > i_row are exactly 0 (masked above).
    const int quarter = tid >> 7;
    const int h       = tid & 127;
    const float* Vb = g_V + b * S_ * H_;
    float acc[8] = {};
    const int jmax = i0 + 7;
    for (int j4 = 4 * quarter; j4 <= jmax; j4 += 16) {
        const float v0 = Vb[(j4 + 0) * H_ + h];
        const float v1 = Vb[(j4 + 1) * H_ + h];
        const float v2 = Vb[(j4 + 2) * H_ + h];
        const float v3 = Vb[(j4 + 3) * H_ + h];
        #pragma unroll
        for (int r = 0; r < 8; r++) {
            const float4 s = *(const float4*)&sScore[r][j4];  // warp-broadcast
            acc[r] = fmaf(s.x, v0, acc[r]);
            acc[r] = fmaf(s.y, v1, acc[r]);
            acc[r] = fmaf(s.z, v2, acc[r]);
            acc[r] = fmaf(s.w, v3, acc[r]);
        }
    }
    if (quarter > 0) {
        #pragma unroll
        for (int r = 0; r < 8; r++) sOp[quarter - 1][r][h] = acc[r];
    }
    __syncthreads();
    if (quarter == 0) {
        #pragma unroll
        for (int r = 0; r < 8; r++) {
            const float s = ((acc[r] + sOp[0][r][h]) + sOp[1][r][h]) + sOp[2][r][h];
            out[(n0 + r) * H_ + h] = s * sInv[r];
        }
    }
}

// ---------------------------------------------------------------------------
// Launch. Inputs per metadata order: x, Wv, Wq, Wk (all float32).
// ---------------------------------------------------------------------------
extern "C" void kernel_launch(void* const* d_in, const int* in_sizes, int n_in,
                              void* d_out, int out_size)
{
    const float* x  = (const float*)d_in[0];
    const float* Wv = (const float*)d_in[1];
    const float* Wq = (const float*)d_in[2];
    const float* Wk = (const float*)d_in[3];
    float* out = (float*)d_out;

    k1_gemm<<<dim3(16, 10, 2), 256>>>(x, Wq, Wk, Wv);
    k2_probs<<<384, 256>>>(x);
    k3a_score<<<dim3(32, 8, 4), 256>>>();
    k3b_out<<<128, 512>>>(out);
}

// round 12
// speedup vs baseline: 1.0456x; 1.0020x over previous
#include <cuda_runtime.h>
#include <math.h>

// Problem constants (fixed by the dataset)
#define B_ 4
#define S_ 256
#define E_ 256
#define H_ 128
#define N_ (B_ * S_)   // 1024 rows total

// Scratch (static device arrays; allocation-free per harness rules)
__device__ float g_ampq2[2][N_ * E_];   // split-K partials
__device__ float g_ampk2[2][N_ * E_];
__device__ float g_V2[2][N_ * H_];
__device__ float g_V[N_ * H_];
__device__ float g_Pq[N_ * E_];   // row-major, query side
__device__ float g_Pk[N_ * E_];   // row-major, key side
__device__ float g_entq[N_];      // sum_e P * lg2(P + 1e-10)
__device__ float g_entk[N_];
__device__ float g_score[N_ * S_];   // masked (pre-normalization) scores

// ---------------------------------------------------------------------------
// Kernel 1 (unchanged, proven): split-K double-buffered GEMM.
// C[1024, 640] = x[1024,256] @ [Wq;Wk;Wv]^T.  64x64 CTA tile, 256 thr,
// 4x4 micro, 16 FFMA per 2 LDS.128, z = K-half; 2-deep smem buffers with
// register prefetch.  Grid 16x10x2 = 320 CTAs.
// ---------------------------------------------------------------------------
__global__ __launch_bounds__(256) void k1_gemm(
    const float* __restrict__ x,
    const float* __restrict__ Wq,
    const float* __restrict__ Wk,
    const float* __restrict__ Wv)
{
    __shared__ float As[2][32][68];  // [buf][k][m], pad keeps float4 alignment
    __shared__ float Bs[2][32][68];  // [buf][k][f]

    const int m0 = blockIdx.x * 64;       // row tile (0..15)
    const int f0 = blockIdx.y * 64;       // f tile (0..9) over concat 640
    const int z  = blockIdx.z;            // K half
    const int kbase = z * 128;

    const float* Wp; float* outp; int fo, ostride;
    if (f0 < 256)      { Wp = Wq; fo = f0;       outp = g_ampq2[z]; ostride = E_; }
    else if (f0 < 512) { Wp = Wk; fo = f0 - 256; outp = g_ampk2[z]; ostride = E_; }
    else               { Wp = Wv; fo = f0 - 512; outp = g_V2[z];    ostride = H_; }

    const int tid  = threadIdx.x;
    const int tx   = tid & 15;            // f micro
    const int ty   = tid >> 4;            // m micro
    const int lrow = tid >> 2;            // 0..63 loader row
    const int lk   = (tid & 3) * 8;       // 0,8,16,24 loader k base

    const float* xg = x  + (m0 + lrow) * E_ + kbase + lk;
    const float* wg = Wp + (fo + lrow) * E_ + kbase + lk;

    float acc[4][4] = {};

    float4 a0 = *(const float4*)(xg);
    float4 a1 = *(const float4*)(xg + 4);
    float4 b0 = *(const float4*)(wg);
    float4 b1 = *(const float4*)(wg + 4);
    {
        As[0][lk+0][lrow] = a0.x; As[0][lk+1][lrow] = a0.y;
        As[0][lk+2][lrow] = a0.z; As[0][lk+3][lrow] = a0.w;
        As[0][lk+4][lrow] = a1.x; As[0][lk+5][lrow] = a1.y;
        As[0][lk+6][lrow] = a1.z; As[0][lk+7][lrow] = a1.w;
        Bs[0][lk+0][lrow] = b0.x; Bs[0][lk+1][lrow] = b0.y;
        Bs[0][lk+2][lrow] = b0.z; Bs[0][lk+3][lrow] = b0.w;
        Bs[0][lk+4][lrow] = b1.x; Bs[0][lk+5][lrow] = b1.y;
        Bs[0][lk+6][lrow] = b1.z; Bs[0][lk+7][lrow] = b1.w;
    }
    __syncthreads();

    #pragma unroll
    for (int c = 0; c < 4; c++) {
        const int buf = c & 1;
        if (c < 3) {                      // prefetch next chunk BEFORE compute
            const int k0 = (c + 1) * 32;
            a0 = *(const float4*)(xg + k0);
            a1 = *(const float4*)(xg + k0 + 4);
            b0 = *(const float4*)(wg + k0);
            b1 = *(const float4*)(wg + k0 + 4);
        }

        #pragma unroll
        for (int kk = 0; kk < 32; kk++) {
            float4 av = *(const float4*)&As[buf][kk][ty * 4];
            float4 bv = *(const float4*)&Bs[buf][kk][tx * 4];
            acc[0][0] = fmaf(av.x, bv.x, acc[0][0]);
            acc[0][1] = fmaf(av.x, bv.y, acc[0][1]);
            acc[0][2] = fmaf(av.x, bv.z, acc[0][2]);
            acc[0][3] = fmaf(av.x, bv.w, acc[0][3]);
            acc[1][0] = fmaf(av.y, bv.x, acc[1][0]);
            acc[1][1] = fmaf(av.y, bv.y, acc[1][1]);
            acc[1][2] = fmaf(av.y, bv.z, acc[1][2]);
            acc[1][3] = fmaf(av.y, bv.w, acc[1][3]);
            acc[2][0] = fmaf(av.z, bv.x, acc[2][0]);
            acc[2][1] = fmaf(av.z, bv.y, acc[2][1]);
            acc[2][2] = fmaf(av.z, bv.z, acc[2][2]);
            acc[2][3] = fmaf(av.z, bv.w, acc[2][3]);
            acc[3][0] = fmaf(av.w, bv.x, acc[3][0]);
            acc[3][1] = fmaf(av.w, bv.y, acc[3][1]);
            acc[3][2] = fmaf(av.w, bv.z, acc[3][2]);
            acc[3][3] = fmaf(av.w, bv.w, acc[3][3]);
        }

        if (c < 3) {                      // stage next chunk into other buffer
            const int nb = buf ^ 1;
            As[nb][lk+0][lrow] = a0.x; As[nb][lk+1][lrow] = a0.y;
            As[nb][lk+2][lrow] = a0.z; As[nb][lk+3][lrow] = a0.w;
            As[nb][lk+4][lrow] = a1.x; As[nb][lk+5][lrow] = a1.y;
            As[nb][lk+6][lrow] = a1.z; As[nb][lk+7][lrow] = a1.w;
            Bs[nb][lk+0][lrow] = b0.x; Bs[nb][lk+1][lrow] = b0.y;
            Bs[nb][lk+2][lrow] = b0.z; Bs[nb][lk+3][lrow] = b0.w;
            Bs[nb][lk+4][lrow] = b1.x; Bs[nb][lk+5][lrow] = b1.y;
            Bs[nb][lk+6][lrow] = b1.z; Bs[nb][lk+7][lrow] = b1.w;
            __syncthreads();
        }
    }

    #pragma unroll
    for (int i = 0; i < 4; i++) {
        const int row = m0 + ty * 4 + i;
        float4 v = make_float4(acc[i][0], acc[i][1], acc[i][2], acc[i][3]);
        *(float4*)&outp[row * ostride + fo + tx * 4] = v;
    }
}

// ---------------------------------------------------------------------------
// Kernel 2 (unchanged, proven): warp-per-row split-K combine + probs +
// entropy.  Regions 0/1 (q/k): amp = part0+part1, P = amp^2/(ssq+EPS*d^2),
// ent = sum P*lg2(P+EPS).  Region 2: V = V0+V1.  grid 384 x 256.
// ---------------------------------------------------------------------------
__global__ __launch_bounds__(256) void k2_probs(const float* __restrict__ x)
{
    const int w    = threadIdx.x >> 5;
    const int lane = threadIdx.x & 31;
    const int slot = blockIdx.x * 8 + w;       // 0..3071
    const int regn = slot >> 10;               // 0 = q, 1 = k, 2 = V-combine
    const int n    = slot & 1023;

    if (regn == 2) {
        const float4* v0 = (const float4*)&g_V2[0][n * H_];
        const float4* v1 = (const float4*)&g_V2[1][n * H_];
        float4*       vo = (float4*)&g_V[n * H_];
        const float4 a = v0[lane], b = v1[lane];
        vo[lane] = make_float4(a.x + b.x, a.y + b.y, a.z + b.z, a.w + b.w);
        return;
    }

    const float* a0 = (regn ? g_ampk2[0] : g_ampq2[0]) + n * E_;
    const float* a1 = (regn ? g_ampk2[1] : g_ampq2[1]) + n * E_;
    float*     Pout = (regn ? g_Pk       : g_Pq)       + n * E_;
    const float* xr = x + n * E_;

    float a[8];
    float ssa = 0.f, ssx = 0.f;
    #pragma unroll
    for (int m = 0; m < 8; m++) {
        a[m] = a0[lane + 32 * m] + a1[lane + 32 * m];
        float xv = xr[lane + 32 * m];
        ssa = fmaf(a[m], a[m], ssa);
        ssx = fmaf(xv, xv, ssx);
    }
    #pragma unroll
    for (int o = 16; o; o >>= 1) {
        ssa += __shfl_xor_sync(0xffffffffu, ssa, o);
        ssx += __shfl_xor_sync(0xffffffffu, ssx, o);
    }
    const float d   = sqrtf(ssx) + 1e-12f;
    const float inv = 1.0f / (ssa + 1e-10f * d * d);

    float ent = 0.f;
    #pragma unroll
    for (int m = 0; m < 8; m++) {
        const float P = a[m] * a[m] * inv;
        ent = fmaf(P, __log2f(P + 1e-10f), ent);
        Pout[lane + 32 * m] = P;
    }
    #pragma unroll
    for (int o = 16; o; o >>= 1)
        ent += __shfl_xor_sync(0xffffffffu, ent, o);
    if (lane == 0) (regn ? g_entk : g_entq)[n] = ent;
}

// ---------------------------------------------------------------------------
// Kernel 3a (unchanged, proven): shuffle-free JS scores.
// CTA = (8-row block, 32-j block, batch); grid (32, 8, 4); fully-masked
// blocks exit.  sPk stride-257 padding -> conflict-free column reads.
// Warp w owns row i0+w, lane owns j0+lane.  MUFU-bound.
// ---------------------------------------------------------------------------
__global__ __launch_bounds__(256) void k3a_score()
{
    const int rb = blockIdx.x;         // row block: rows 8rb..8rb+7
    const int jb = blockIdx.y;         // j block:   js  32jb..32jb+31
    const int b  = blockIdx.z;
    if (jb > (rb >> 2)) return;        // whole block above the diagonal

    __shared__ float sPk[32][257];     // [j_local][e], stride 257
    __shared__ float sP[8][256];       // [row_local][e]
    __shared__ float sHk[32];

    const int tid  = threadIdx.x;
    const int w    = tid >> 5;
    const int lane = tid & 31;
    const int i0 = rb * 8, j0 = jb * 32;

    // Stage Pk rows (warp w -> rows 4w..4w+3; 8 lanes per row, coalesced 128B)
    {
        const int row = 4 * w + (lane >> 3);
        const int fb  = lane & 7;
        const float* src = g_Pk + (b * S_ + j0 + row) * E_;
        #pragma unroll
        for (int it = 0; it < 8; it++) {
            const int f = fb + 8 * it;          // float4 index within row
            float4 v = *(const float4*)(src + 4 * f);
            sPk[row][4*f+0] = v.x; sPk[row][4*f+1] = v.y;
            sPk[row][4*f+2] = v.z; sPk[row][4*f+3] = v.w;
        }
    }
    // Stage Pq rows (warp w -> row w, two float4 per lane, coalesced)
    {
        const float* src = g_Pq + (b * S_ + i0 + w) * E_;
        *(float4*)&sP[w][4 * lane]        = *(const float4*)(src + 4 * lane);
        *(float4*)&sP[w][128 + 4 * lane]  = *(const float4*)(src + 128 + 4 * lane);
    }
    if (tid < 32) sHk[tid] = g_entk[b * S_ + j0 + tid];
    __syncthreads();

    const float hq = g_entq[b * S_ + i0 + w];
    const float hk = sHk[lane];

    float ac0 = 0.f, ac1 = 0.f, ac2 = 0.f, ac3 = 0.f;
    #pragma unroll 8
    for (int e = 0; e < E_; e += 4) {
        const float4 p = *(const float4*)&sP[w][e];
        const float s0 = p.x + sPk[lane][e + 0];
        const float s1 = p.y + sPk[lane][e + 1];
        const float s2 = p.z + sPk[lane][e + 2];
        const float s3 = p.w + sPk[lane][e + 3];
        ac0 = fmaf(s0, __log2f(fmaf(0.5f, s0, 1e-10f)), ac0);
        ac1 = fmaf(s1, __log2f(fmaf(0.5f, s1, 1e-10f)), ac1);
        ac2 = fmaf(s2, __log2f(fmaf(0.5f, s2, 1e-10f)), ac2);
        ac3 = fmaf(s3, __log2f(fmaf(0.5f, s3, 1e-10f)), ac3);
    }
    const float acc = (ac0 + ac1) + (ac2 + ac3);

    const int i = i0 + w, j = j0 + lane;
    const float HL = 0.34657359028f;             // 0.5 * ln(2)
    const float score = 1.0f - HL * (hq + hk - acc);
    g_score[(b * S_ + i) * S_ + j] = (j <= i) ? score : 0.0f;   // coalesced
}

// ---------------------------------------------------------------------------
// Kernel 3b v4: blocked row-normalize + attn @ V, COMPILE-TIME trip count.
// R11 was still latency-bound (occ 25%, issue 18%): the j-loop bound was
// runtime (jmax = i0+7), so ptxas couldn't unroll -> MLP~1.  Masked scores
// are exactly 0 for j > i_row, and V rows 0..255 are always valid, so every
// quarter now runs the FULL j range unconditionally: FMA work doubles
// (33.5M, still ~2k chip-cycles) but the loop is fully unrolled (16 fixed
// iterations), LDGs front-batch, and exposed latency collapses.
// Grid 128 x 512 threads; thread = (quarter, h), 8 row accumulators.
// ---------------------------------------------------------------------------
__global__ __launch_bounds__(512) void k3b_out(float* __restrict__ out)
{
    __shared__ float sScore[8][256];    //  8 KB
    __shared__ float sOp[3][8][128];    // 12 KB partial O from quarters 1..3
    __shared__ float sInv[8];

    const int c  = blockIdx.x;        // 0..127
    const int n0 = c * 8;
    const int b  = n0 >> 8;
    const int i0 = n0 & 255;          // rows i0..i0+7 (same batch: 8 | 256)
    const int tid  = threadIdx.x;
    const int w    = tid >> 5;
    const int lane = tid & 31;

    // Warps 0..7: stage + mask scores for row w, and compute the row L1 sum
    // from the registers just loaded (no smem read-back needed).
    if (w < 8) {
        const int i_row = i0 + w;
        const float* src = g_score + (n0 + w) * S_;
        float rs = 0.f;
        #pragma unroll
        for (int t = 0; t < 2; t++) {
            const int j4 = 4 * lane + 128 * t;
            float4 v = *(const float4*)(src + j4);
            v.x = (j4 + 0 <= i_row) ? v.x : 0.f;
            v.y = (j4 + 1 <= i_row) ? v.y : 0.f;
            v.z = (j4 + 2 <= i_row) ? v.z : 0.f;
            v.w = (j4 + 3 <= i_row) ? v.w : 0.f;
            *(float4*)&sScore[w][j4] = v;
            rs += fabsf(v.x) + fabsf(v.y) + fabsf(v.z) + fabsf(v.w);
        }
        #pragma unroll
        for (int o = 16; o; o >>= 1) rs += __shfl_xor_sync(0xffffffffu, rs, o);
        if (lane == 0) sInv[w] = 1.0f / fmaxf(rs, 1e-12f);
    }
    __syncthreads();

    // V accumulation over the FULL j range (masked scores are exact zeros for
    // j > i_row, so the extra iterations add 0).  Quarter q owns j4 = 4q+16t,
    // t = 0..15 -- a compile-time trip count, fully unrolled.
    const int quarter = tid >> 7;
    const int h       = tid & 127;
    const float* Vb = g_V + b * S_ * H_ + h;
    float acc[8] = {};
    #pragma unroll
    for (int t = 0; t < 16; t++) {
        const int j4 = 4 * quarter + 16 * t;
        const float v0 = Vb[(j4 + 0) * H_];
        const float v1 = Vb[(j4 + 1) * H_];
        const float v2 = Vb[(j4 + 2) * H_];
        const float v3 = Vb[(j4 + 3) * H_];
        #pragma unroll
        for (int r = 0; r < 8; r++) {
            const float4 s = *(const float4*)&sScore[r][j4];  // warp-broadcast
            acc[r] = fmaf(s.x, v0, acc[r]);
            acc[r] = fmaf(s.y, v1, acc[r]);
            acc[r] = fmaf(s.z, v2, acc[r]);
            acc[r] = fmaf(s.w, v3, acc[r]);
        }
    }
    if (quarter > 0) {
        #pragma unroll
        for (int r = 0; r < 8; r++) sOp[quarter - 1][r][h] = acc[r];
    }
    __syncthreads();
    if (quarter == 0) {
        #pragma unroll
        for (int r = 0; r < 8; r++) {
            const float s = ((acc[r] + sOp[0][r][h]) + sOp[1][r][h]) + sOp[2][r][h];
            out[(n0 + r) * H_ + h] = s * sInv[r];
        }
    }
}

// ---------------------------------------------------------------------------
// Launch. Inputs per metadata order: x, Wv, Wq, Wk (all float32).
// ---------------------------------------------------------------------------
extern "C" void kernel_launch(void* const* d_in, const int* in_sizes, int n_in,
                              void* d_out, int out_size)
{
    const float* x  = (const float*)d_in[0];
    const float* Wv = (const float*)d_in[1];
    const float* Wq = (const float*)d_in[2];
    const float* Wk = (const float*)d_in[3];
    float* out = (float*)d_out;

    k1_gemm<<<dim3(16, 10, 2), 256>>>(x, Wq, Wk, Wv);
    k2_probs<<<384, 256>>>(x);
    k3a_score<<<dim3(32, 8, 4), 256>>>();
    k3b_out<<<128, 512>>>(out);
}

// round 13
// speedup vs baseline: 1.0908x; 1.0433x over previous
#include <cuda_runtime.h>
#include <math.h>

// Problem constants (fixed by the dataset)
#define B_ 4
#define S_ 256
#define E_ 256
#define H_ 128
#define N_ (B_ * S_)   // 1024 rows total

// Scratch (static device arrays; allocation-free per harness rules)
__device__ float g_ampq2[2][N_ * E_];   // split-K partials
__device__ float g_ampk2[2][N_ * E_];
__device__ float g_V2[2][N_ * H_];
__device__ float g_V[N_ * H_];
__device__ float g_Pq[N_ * E_];   // row-major, query side
__device__ float g_Pk[N_ * E_];   // row-major, key side
__device__ float g_entq[N_];      // sum_e P * lg2(P + 1e-10)
__device__ float g_entk[N_];
__device__ float g_score[N_ * S_];   // masked (pre-normalization) scores

// ---------------------------------------------------------------------------
// Kernel 1 (unchanged, proven): split-K double-buffered GEMM.
// C[1024, 640] = x[1024,256] @ [Wq;Wk;Wv]^T.  64x64 CTA tile, 256 thr,
// 4x4 micro, 16 FFMA per 2 LDS.128, z = K-half; 2-deep smem buffers with
// register prefetch.  Grid 16x10x2 = 320 CTAs.
// ---------------------------------------------------------------------------
__global__ __launch_bounds__(256) void k1_gemm(
    const float* __restrict__ x,
    const float* __restrict__ Wq,
    const float* __restrict__ Wk,
    const float* __restrict__ Wv)
{
    __shared__ float As[2][32][68];  // [buf][k][m], pad keeps float4 alignment
    __shared__ float Bs[2][32][68];  // [buf][k][f]

    const int m0 = blockIdx.x * 64;       // row tile (0..15)
    const int f0 = blockIdx.y * 64;       // f tile (0..9) over concat 640
    const int z  = blockIdx.z;            // K half
    const int kbase = z * 128;

    const float* Wp; float* outp; int fo, ostride;
    if (f0 < 256)      { Wp = Wq; fo = f0;       outp = g_ampq2[z]; ostride = E_; }
    else if (f0 < 512) { Wp = Wk; fo = f0 - 256; outp = g_ampk2[z]; ostride = E_; }
    else               { Wp = Wv; fo = f0 - 512; outp = g_V2[z];    ostride = H_; }

    const int tid  = threadIdx.x;
    const int tx   = tid & 15;            // f micro
    const int ty   = tid >> 4;            // m micro
    const int lrow = tid >> 2;            // 0..63 loader row
    const int lk   = (tid & 3) * 8;       // 0,8,16,24 loader k base

    const float* xg = x  + (m0 + lrow) * E_ + kbase + lk;
    const float* wg = Wp + (fo + lrow) * E_ + kbase + lk;

    float acc[4][4] = {};

    float4 a0 = *(const float4*)(xg);
    float4 a1 = *(const float4*)(xg + 4);
    float4 b0 = *(const float4*)(wg);
    float4 b1 = *(const float4*)(wg + 4);
    {
        As[0][lk+0][lrow] = a0.x; As[0][lk+1][lrow] = a0.y;
        As[0][lk+2][lrow] = a0.z; As[0][lk+3][lrow] = a0.w;
        As[0][lk+4][lrow] = a1.x; As[0][lk+5][lrow] = a1.y;
        As[0][lk+6][lrow] = a1.z; As[0][lk+7][lrow] = a1.w;
        Bs[0][lk+0][lrow] = b0.x; Bs[0][lk+1][lrow] = b0.y;
        Bs[0][lk+2][lrow] = b0.z; Bs[0][lk+3][lrow] = b0.w;
        Bs[0][lk+4][lrow] = b1.x; Bs[0][lk+5][lrow] = b1.y;
        Bs[0][lk+6][lrow] = b1.z; Bs[0][lk+7][lrow] = b1.w;
    }
    __syncthreads();

    #pragma unroll
    for (int c = 0; c < 4; c++) {
        const int buf = c & 1;
        if (c < 3) {                      // prefetch next chunk BEFORE compute
            const int k0 = (c + 1) * 32;
            a0 = *(const float4*)(xg + k0);
            a1 = *(const float4*)(xg + k0 + 4);
            b0 = *(const float4*)(wg + k0);
            b1 = *(const float4*)(wg + k0 + 4);
        }

        #pragma unroll
        for (int kk = 0; kk < 32; kk++) {
            float4 av = *(const float4*)&As[buf][kk][ty * 4];
            float4 bv = *(const float4*)&Bs[buf][kk][tx * 4];
            acc[0][0] = fmaf(av.x, bv.x, acc[0][0]);
            acc[0][1] = fmaf(av.x, bv.y, acc[0][1]);
            acc[0][2] = fmaf(av.x, bv.z, acc[0][2]);
            acc[0][3] = fmaf(av.x, bv.w, acc[0][3]);
            acc[1][0] = fmaf(av.y, bv.x, acc[1][0]);
            acc[1][1] = fmaf(av.y, bv.y, acc[1][1]);
            acc[1][2] = fmaf(av.y, bv.z, acc[1][2]);
            acc[1][3] = fmaf(av.y, bv.w, acc[1][3]);
            acc[2][0] = fmaf(av.z, bv.x, acc[2][0]);
            acc[2][1] = fmaf(av.z, bv.y, acc[2][1]);
            acc[2][2] = fmaf(av.z, bv.z, acc[2][2]);
            acc[2][3] = fmaf(av.z, bv.w, acc[2][3]);
            acc[3][0] = fmaf(av.w, bv.x, acc[3][0]);
            acc[3][1] = fmaf(av.w, bv.y, acc[3][1]);
            acc[3][2] = fmaf(av.w, bv.z, acc[3][2]);
            acc[3][3] = fmaf(av.w, bv.w, acc[3][3]);
        }

        if (c < 3) {                      // stage next chunk into other buffer
            const int nb = buf ^ 1;
            As[nb][lk+0][lrow] = a0.x; As[nb][lk+1][lrow] = a0.y;
            As[nb][lk+2][lrow] = a0.z; As[nb][lk+3][lrow] = a0.w;
            As[nb][lk+4][lrow] = a1.x; As[nb][lk+5][lrow] = a1.y;
            As[nb][lk+6][lrow] = a1.z; As[nb][lk+7][lrow] = a1.w;
            Bs[nb][lk+0][lrow] = b0.x; Bs[nb][lk+1][lrow] = b0.y;
            Bs[nb][lk+2][lrow] = b0.z; Bs[nb][lk+3][lrow] = b0.w;
            Bs[nb][lk+4][lrow] = b1.x; Bs[nb][lk+5][lrow] = b1.y;
            Bs[nb][lk+6][lrow] = b1.z; Bs[nb][lk+7][lrow] = b1.w;
            __syncthreads();
        }
    }

    #pragma unroll
    for (int i = 0; i < 4; i++) {
        const int row = m0 + ty * 4 + i;
        float4 v = make_float4(acc[i][0], acc[i][1], acc[i][2], acc[i][3]);
        *(float4*)&outp[row * ostride + fo + tx * 4] = v;
    }
}

// ---------------------------------------------------------------------------
// Kernel 2 (unchanged, proven): warp-per-row split-K combine + probs +
// entropy.  Regions 0/1 (q/k): amp = part0+part1, P = amp^2/(ssq+EPS*d^2),
// ent = sum P*lg2(P+EPS).  Region 2: V = V0+V1.  grid 384 x 256.
// ---------------------------------------------------------------------------
__global__ __launch_bounds__(256) void k2_probs(const float* __restrict__ x)
{
    const int w    = threadIdx.x >> 5;
    const int lane = threadIdx.x & 31;
    const int slot = blockIdx.x * 8 + w;       // 0..3071
    const int regn = slot >> 10;               // 0 = q, 1 = k, 2 = V-combine
    const int n    = slot & 1023;

    if (regn == 2) {
        const float4* v0 = (const float4*)&g_V2[0][n * H_];
        const float4* v1 = (const float4*)&g_V2[1][n * H_];
        float4*       vo = (float4*)&g_V[n * H_];
        const float4 a = v0[lane], b = v1[lane];
        vo[lane] = make_float4(a.x + b.x, a.y + b.y, a.z + b.z, a.w + b.w);
        return;
    }

    const float* a0 = (regn ? g_ampk2[0] : g_ampq2[0]) + n * E_;
    const float* a1 = (regn ? g_ampk2[1] : g_ampq2[1]) + n * E_;
    float*     Pout = (regn ? g_Pk       : g_Pq)       + n * E_;
    const float* xr = x + n * E_;

    float a[8];
    float ssa = 0.f, ssx = 0.f;
    #pragma unroll
    for (int m = 0; m < 8; m++) {
        a[m] = a0[lane + 32 * m] + a1[lane + 32 * m];
        float xv = xr[lane + 32 * m];
        ssa = fmaf(a[m], a[m], ssa);
        ssx = fmaf(xv, xv, ssx);
    }
    #pragma unroll
    for (int o = 16; o; o >>= 1) {
        ssa += __shfl_xor_sync(0xffffffffu, ssa, o);
        ssx += __shfl_xor_sync(0xffffffffu, ssx, o);
    }
    const float d   = sqrtf(ssx) + 1e-12f;
    const float inv = 1.0f / (ssa + 1e-10f * d * d);

    float ent = 0.f;
    #pragma unroll
    for (int m = 0; m < 8; m++) {
        const float P = a[m] * a[m] * inv;
        ent = fmaf(P, __log2f(P + 1e-10f), ent);
        Pout[lane + 32 * m] = P;
    }
    #pragma unroll
    for (int o = 16; o; o >>= 1)
        ent += __shfl_xor_sync(0xffffffffu, ent, o);
    if (lane == 0) (regn ? g_entk : g_entq)[n] = ent;
}

// ---------------------------------------------------------------------------
// Kernel 3a (unchanged, proven): shuffle-free JS scores.
// CTA = (8-row block, 32-j block, batch); grid (32, 8, 4); fully-masked
// blocks exit.  sPk stride-257 padding -> conflict-free column reads.
// Warp w owns row i0+w, lane owns j0+lane.  MUFU-bound.
// ---------------------------------------------------------------------------
__global__ __launch_bounds__(256) void k3a_score()
{
    const int rb = blockIdx.x;         // row block: rows 8rb..8rb+7
    const int jb = blockIdx.y;         // j block:   js  32jb..32jb+31
    const int b  = blockIdx.z;
    if (jb > (rb >> 2)) return;        // whole block above the diagonal

    __shared__ float sPk[32][257];     // [j_local][e], stride 257
    __shared__ float sP[8][256];       // [row_local][e]
    __shared__ float sHk[32];

    const int tid  = threadIdx.x;
    const int w    = tid >> 5;
    const int lane = tid & 31;
    const int i0 = rb * 8, j0 = jb * 32;

    // Stage Pk rows (warp w -> rows 4w..4w+3; 8 lanes per row, coalesced 128B)
    {
        const int row = 4 * w + (lane >> 3);
        const int fb  = lane & 7;
        const float* src = g_Pk + (b * S_ + j0 + row) * E_;
        #pragma unroll
        for (int it = 0; it < 8; it++) {
            const int f = fb + 8 * it;          // float4 index within row
            float4 v = *(const float4*)(src + 4 * f);
            sPk[row][4*f+0] = v.x; sPk[row][4*f+1] = v.y;
            sPk[row][4*f+2] = v.z; sPk[row][4*f+3] = v.w;
        }
    }
    // Stage Pq rows (warp w -> row w, two float4 per lane, coalesced)
    {
        const float* src = g_Pq + (b * S_ + i0 + w) * E_;
        *(float4*)&sP[w][4 * lane]        = *(const float4*)(src + 4 * lane);
        *(float4*)&sP[w][128 + 4 * lane]  = *(const float4*)(src + 128 + 4 * lane);
    }
    if (tid < 32) sHk[tid] = g_entk[b * S_ + j0 + tid];
    __syncthreads();

    const float hq = g_entq[b * S_ + i0 + w];
    const float hk = sHk[lane];

    float ac0 = 0.f, ac1 = 0.f, ac2 = 0.f, ac3 = 0.f;
    #pragma unroll 8
    for (int e = 0; e < E_; e += 4) {
        const float4 p = *(const float4*)&sP[w][e];
        const float s0 = p.x + sPk[lane][e + 0];
        const float s1 = p.y + sPk[lane][e + 1];
        const float s2 = p.z + sPk[lane][e + 2];
        const float s3 = p.w + sPk[lane][e + 3];
        ac0 = fmaf(s0, __log2f(fmaf(0.5f, s0, 1e-10f)), ac0);
        ac1 = fmaf(s1, __log2f(fmaf(0.5f, s1, 1e-10f)), ac1);
        ac2 = fmaf(s2, __log2f(fmaf(0.5f, s2, 1e-10f)), ac2);
        ac3 = fmaf(s3, __log2f(fmaf(0.5f, s3, 1e-10f)), ac3);
    }
    const float acc = (ac0 + ac1) + (ac2 + ac3);

    const int i = i0 + w, j = j0 + lane;
    const float HL = 0.34657359028f;             // 0.5 * ln(2)
    const float score = 1.0f - HL * (hq + hk - acc);
    g_score[(b * S_ + i) * S_ + j] = (j <= i) ? score : 0.0f;   // coalesced
}

// ---------------------------------------------------------------------------
// Kernel 3b v5: blocked row-normalize + attn @ V, short critical path.
// R12 analysis: grid 128 (< 148 SMs), 1 CTA/SM, whole kernel = one long
// dependency chain (~26k cyc vs ~3k issue floor); regs=39 showed ptxas had
// serialized the loads.  Now: grid 256 (4 rows/CTA), 512 threads, j-range
// split 8 WAYS (way = tid>>6 owns 32 j's, each thread covers h and h+64).
// Per-thread: 8 fixed iters x (8 LDG + 4 broadcast-LDS.128 + 32 FMA),
// ~360 instr, low register pressure.  Partials combined via 14 KB smem.
// V is L2-resident (512 KB) so the 2x read amplification is ~free.
// ---------------------------------------------------------------------------
__global__ __launch_bounds__(512) void k3b_out(float* __restrict__ out)
{
    __shared__ float sScore[4][256];    //  4 KB
    __shared__ float sOp[7][4][128];    // 14 KB partials from ways 1..7
    __shared__ float sInv[4];

    const int c  = blockIdx.x;        // 0..255
    const int n0 = c * 4;
    const int b  = n0 >> 8;
    const int i0 = n0 & 255;          // rows i0..i0+3 (same batch: 4 | 256)
    const int tid  = threadIdx.x;
    const int w    = tid >> 5;
    const int lane = tid & 31;

    // Warps 0..3: stage + mask scores for row w and compute the row L1 sum
    // from the registers just loaded.
    if (w < 4) {
        const int i_row = i0 + w;
        const float* src = g_score + (n0 + w) * S_;
        float rs = 0.f;
        #pragma unroll
        for (int t = 0; t < 2; t++) {
            const int j4 = 4 * lane + 128 * t;
            float4 v = *(const float4*)(src + j4);
            v.x = (j4 + 0 <= i_row) ? v.x : 0.f;
            v.y = (j4 + 1 <= i_row) ? v.y : 0.f;
            v.z = (j4 + 2 <= i_row) ? v.z : 0.f;
            v.w = (j4 + 3 <= i_row) ? v.w : 0.f;
            *(float4*)&sScore[w][j4] = v;
            rs += fabsf(v.x) + fabsf(v.y) + fabsf(v.z) + fabsf(v.w);
        }
        #pragma unroll
        for (int o = 16; o; o >>= 1) rs += __shfl_xor_sync(0xffffffffu, rs, o);
        if (lane == 0) sInv[w] = 1.0f / fmaxf(rs, 1e-12f);
    }
    __syncthreads();

    // V accumulation over the FULL j range (masked scores are exact zeros
    // for j > i_row).  way = tid>>6 (uniform per warp -> sScore reads are
    // warp-broadcast); thread handles h = tid&63 and h+64.
    const int way = tid >> 6;         // 0..7
    const int h   = tid & 63;         // 0..63
    const float* Vb = g_V + b * S_ * H_ + h;
    float acc[4][2] = {};
    #pragma unroll
    for (int t = 0; t < 8; t++) {
        const int j4 = 4 * way + 32 * t;
        float v0a = Vb[(j4 + 0) * H_],  v0b = Vb[(j4 + 0) * H_ + 64];
        float v1a = Vb[(j4 + 1) * H_],  v1b = Vb[(j4 + 1) * H_ + 64];
        float v2a = Vb[(j4 + 2) * H_],  v2b = Vb[(j4 + 2) * H_ + 64];
        float v3a = Vb[(j4 + 3) * H_],  v3b = Vb[(j4 + 3) * H_ + 64];
        #pragma unroll
        for (int r = 0; r < 4; r++) {
            const float4 s = *(const float4*)&sScore[r][j4];  // warp-broadcast
            acc[r][0] = fmaf(s.x, v0a, acc[r][0]);
            acc[r][1] = fmaf(s.x, v0b, acc[r][1]);
            acc[r][0] = fmaf(s.y, v1a, acc[r][0]);
            acc[r][1] = fmaf(s.y, v1b, acc[r][1]);
            acc[r][0] = fmaf(s.z, v2a, acc[r][0]);
            acc[r][1] = fmaf(s.z, v2b, acc[r][1]);
            acc[r][0] = fmaf(s.w, v3a, acc[r][0]);
            acc[r][1] = fmaf(s.w, v3b, acc[r][1]);
        }
    }
    if (way > 0) {
        #pragma unroll
        for (int r = 0; r < 4; r++) {
            sOp[way - 1][r][h]      = acc[r][0];
            sOp[way - 1][r][h + 64] = acc[r][1];
        }
    }
    __syncthreads();
    if (way == 0) {
        #pragma unroll
        for (int r = 0; r < 4; r++) {
            float s0 = acc[r][0], s1 = acc[r][1];
            #pragma unroll
            for (int q = 0; q < 7; q++) {
                s0 += sOp[q][r][h];
                s1 += sOp[q][r][h + 64];
            }
            out[(n0 + r) * H_ + h]      = s0 * sInv[r];
            out[(n0 + r) * H_ + h + 64] = s1 * sInv[r];
        }
    }
}

// ---------------------------------------------------------------------------
// Launch. Inputs per metadata order: x, Wv, Wq, Wk (all float32).
// ---------------------------------------------------------------------------
extern "C" void kernel_launch(void* const* d_in, const int* in_sizes, int n_in,
                              void* d_out, int out_size)
{
    const float* x  = (const float*)d_in[0];
    const float* Wv = (const float*)d_in[1];
    const float* Wq = (const float*)d_in[2];
    const float* Wk = (const float*)d_in[3];
    float* out = (float*)d_out;

    k1_gemm<<<dim3(16, 10, 2), 256>>>(x, Wq, Wk, Wv);
    k2_probs<<<384, 256>>>(x);
    k3a_score<<<dim3(32, 8, 4), 256>>>();
    k3b_out<<<256, 512>>>(out);
}

// round 15
// speedup vs baseline: 1.1058x; 1.0137x over previous
#include <cuda_runtime.h>
#include <math.h>

// Problem constants (fixed by the dataset)
#define B_ 4
#define S_ 256
#define E_ 256
#define H_ 128
#define N_ (B_ * S_)   // 1024 rows total

// Scratch (static device arrays; allocation-free per harness rules)
__device__ float g_ampq2[2][N_ * E_];   // split-K partials
__device__ float g_ampk2[2][N_ * E_];
__device__ float g_V2[2][N_ * H_];
__device__ float g_V[N_ * H_];
__device__ float g_Pq[N_ * E_];   // row-major, query side
__device__ float g_Pk[N_ * E_];   // row-major, key side
__device__ float g_entq[N_];      // sum_e P * lg2(P + 1e-10)
__device__ float g_entk[N_];
__device__ float g_Op[8][N_][H_];   // partial O per j-block (4 MB)
__device__ float g_rsp[8][N_];      // partial L1 row sums per j-block

// ---------------------------------------------------------------------------
// Kernel 1 (unchanged, proven): split-K double-buffered GEMM.
// C[1024, 640] = x[1024,256] @ [Wq;Wk;Wv]^T.  64x64 CTA tile, 256 thr,
// 4x4 micro, 16 FFMA per 2 LDS.128, z = K-half; 2-deep smem buffers with
// register prefetch.  Grid 16x10x2 = 320 CTAs.
// ---------------------------------------------------------------------------
__global__ __launch_bounds__(256) void k1_gemm(
    const float* __restrict__ x,
    const float* __restrict__ Wq,
    const float* __restrict__ Wk,
    const float* __restrict__ Wv)
{
    __shared__ float As[2][32][68];  // [buf][k][m], pad keeps float4 alignment
    __shared__ float Bs[2][32][68];  // [buf][k][f]

    const int m0 = blockIdx.x * 64;       // row tile (0..15)
    const int f0 = blockIdx.y * 64;       // f tile (0..9) over concat 640
    const int z  = blockIdx.z;            // K half
    const int kbase = z * 128;

    const float* Wp; float* outp; int fo, ostride;
    if (f0 < 256)      { Wp = Wq; fo = f0;       outp = g_ampq2[z]; ostride = E_; }
    else if (f0 < 512) { Wp = Wk; fo = f0 - 256; outp = g_ampk2[z]; ostride = E_; }
    else               { Wp = Wv; fo = f0 - 512; outp = g_V2[z];    ostride = H_; }

    const int tid  = threadIdx.x;
    const int tx   = tid & 15;            // f micro
    const int ty   = tid >> 4;            // m micro
    const int lrow = tid >> 2;            // 0..63 loader row
    const int lk   = (tid & 3) * 8;       // 0,8,16,24 loader k base

    const float* xg = x  + (m0 + lrow) * E_ + kbase + lk;
    const float* wg = Wp + (fo + lrow) * E_ + kbase + lk;

    float acc[4][4] = {};

    float4 a0 = *(const float4*)(xg);
    float4 a1 = *(const float4*)(xg + 4);
    float4 b0 = *(const float4*)(wg);
    float4 b1 = *(const float4*)(wg + 4);
    {
        As[0][lk+0][lrow] = a0.x; As[0][lk+1][lrow] = a0.y;
        As[0][lk+2][lrow] = a0.z; As[0][lk+3][lrow] = a0.w;
        As[0][lk+4][lrow] = a1.x; As[0][lk+5][lrow] = a1.y;
        As[0][lk+6][lrow] = a1.z; As[0][lk+7][lrow] = a1.w;
        Bs[0][lk+0][lrow] = b0.x; Bs[0][lk+1][lrow] = b0.y;
        Bs[0][lk+2][lrow] = b0.z; Bs[0][lk+3][lrow] = b0.w;
        Bs[0][lk+4][lrow] = b1.x; Bs[0][lk+5][lrow] = b1.y;
        Bs[0][lk+6][lrow] = b1.z; Bs[0][lk+7][lrow] = b1.w;
    }
    __syncthreads();

    #pragma unroll
    for (int c = 0; c < 4; c++) {
        const int buf = c & 1;
        if (c < 3) {                      // prefetch next chunk BEFORE compute
            const int k0 = (c + 1) * 32;
            a0 = *(const float4*)(xg + k0);
            a1 = *(const float4*)(xg + k0 + 4);
            b0 = *(const float4*)(wg + k0);
            b1 = *(const float4*)(wg + k0 + 4);
        }

        #pragma unroll
        for (int kk = 0; kk < 32; kk++) {
            float4 av = *(const float4*)&As[buf][kk][ty * 4];
            float4 bv = *(const float4*)&Bs[buf][kk][tx * 4];
            acc[0][0] = fmaf(av.x, bv.x, acc[0][0]);
            acc[0][1] = fmaf(av.x, bv.y, acc[0][1]);
            acc[0][2] = fmaf(av.x, bv.z, acc[0][2]);
            acc[0][3] = fmaf(av.x, bv.w, acc[0][3]);
            acc[1][0] = fmaf(av.y, bv.x, acc[1][0]);
            acc[1][1] = fmaf(av.y, bv.y, acc[1][1]);
            acc[1][2] = fmaf(av.y, bv.z, acc[1][2]);
            acc[1][3] = fmaf(av.y, bv.w, acc[1][3]);
            acc[2][0] = fmaf(av.z, bv.x, acc[2][0]);
            acc[2][1] = fmaf(av.z, bv.y, acc[2][1]);
            acc[2][2] = fmaf(av.z, bv.z, acc[2][2]);
            acc[2][3] = fmaf(av.z, bv.w, acc[2][3]);
            acc[3][0] = fmaf(av.w, bv.x, acc[3][0]);
            acc[3][1] = fmaf(av.w, bv.y, acc[3][1]);
            acc[3][2] = fmaf(av.w, bv.z, acc[3][2]);
            acc[3][3] = fmaf(av.w, bv.w, acc[3][3]);
        }

        if (c < 3) {                      // stage next chunk into other buffer
            const int nb = buf ^ 1;
            As[nb][lk+0][lrow] = a0.x; As[nb][lk+1][lrow] = a0.y;
            As[nb][lk+2][lrow] = a0.z; As[nb][lk+3][lrow] = a0.w;
            As[nb][lk+4][lrow] = a1.x; As[nb][lk+5][lrow] = a1.y;
            As[nb][lk+6][lrow] = a1.z; As[nb][lk+7][lrow] = a1.w;
            Bs[nb][lk+0][lrow] = b0.x; Bs[nb][lk+1][lrow] = b0.y;
            Bs[nb][lk+2][lrow] = b0.z; Bs[nb][lk+3][lrow] = b0.w;
            Bs[nb][lk+4][lrow] = b1.x; Bs[nb][lk+5][lrow] = b1.y;
            Bs[nb][lk+6][lrow] = b1.z; Bs[nb][lk+7][lrow] = b1.w;
            __syncthreads();
        }
    }

    #pragma unroll
    for (int i = 0; i < 4; i++) {
        const int row = m0 + ty * 4 + i;
        float4 v = make_float4(acc[i][0], acc[i][1], acc[i][2], acc[i][3]);
        *(float4*)&outp[row * ostride + fo + tx * 4] = v;
    }
}

// ---------------------------------------------------------------------------
// Kernel 2 (unchanged, proven): warp-per-row split-K combine + probs +
// entropy.  Regions 0/1 (q/k): amp = part0+part1, P = amp^2/(ssq+EPS*d^2),
// ent = sum P*lg2(P+EPS).  Region 2: V = V0+V1.  grid 384 x 256.
// ---------------------------------------------------------------------------
__global__ __launch_bounds__(256) void k2_probs(const float* __restrict__ x)
{
    const int w    = threadIdx.x >> 5;
    const int lane = threadIdx.x & 31;
    const int slot = blockIdx.x * 8 + w;       // 0..3071
    const int regn = slot >> 10;               // 0 = q, 1 = k, 2 = V-combine
    const int n    = slot & 1023;

    if (regn == 2) {
        const float4* v0 = (const float4*)&g_V2[0][n * H_];
        const float4* v1 = (const float4*)&g_V2[1][n * H_];
        float4*       vo = (float4*)&g_V[n * H_];
        const float4 a = v0[lane], b = v1[lane];
        vo[lane] = make_float4(a.x + b.x, a.y + b.y, a.z + b.z, a.w + b.w);
        return;
    }

    const float* a0 = (regn ? g_ampk2[0] : g_ampq2[0]) + n * E_;
    const float* a1 = (regn ? g_ampk2[1] : g_ampq2[1]) + n * E_;
    float*     Pout = (regn ? g_Pk       : g_Pq)       + n * E_;
    const float* xr = x + n * E_;

    float a[8];
    float ssa = 0.f, ssx = 0.f;
    #pragma unroll
    for (int m = 0; m < 8; m++) {
        a[m] = a0[lane + 32 * m] + a1[lane + 32 * m];
        float xv = xr[lane + 32 * m];
        ssa = fmaf(a[m], a[m], ssa);
        ssx = fmaf(xv, xv, ssx);
    }
    #pragma unroll
    for (int o = 16; o; o >>= 1) {
        ssa += __shfl_xor_sync(0xffffffffu, ssa, o);
        ssx += __shfl_xor_sync(0xffffffffu, ssx, o);
    }
    const float d   = sqrtf(ssx) + 1e-12f;
    const float inv = 1.0f / (ssa + 1e-10f * d * d);

    float ent = 0.f;
    #pragma unroll
    for (int m = 0; m < 8; m++) {
        const float P = a[m] * a[m] * inv;
        ent = fmaf(P, __log2f(P + 1e-10f), ent);
        Pout[lane + 32 * m] = P;
    }
    #pragma unroll
    for (int o = 16; o; o >>= 1)
        ent += __shfl_xor_sync(0xffffffffu, ent, o);
    if (lane == 0) (regn ? g_entk : g_entq)[n] = ent;
}

// ---------------------------------------------------------------------------
// Kernel 3 (fused, FIXED): JS scores + masked score-block @ V-block.
// R14 bug: sPk was declared [32][129] but indexed to e=255 -> smem overflow,
// garbage scores.  Fix: full-size sPk[32][257] (conflict-free: (lane+e)%32
// distinct), and the V block TIME-MULTIPLEXES the same storage -- sPk is
// dead after the score phase.  V is loaded into 16 registers per thread at
// kernel ENTRY (LDGs in flight through the entire staging + MUFU score
// phase), then dumped to the aliased smem with pure STS after a sync.
// Static smem 41.25 KB < 48 KB.
// CTA = (8-row block, 32-j block, batch); grid (32, 8, 4).
// ---------------------------------------------------------------------------
__global__ __launch_bounds__(256) void k3_sv()
{
    const int rb = blockIdx.x;         // row block: rows 8rb..8rb+7
    const int jb = blockIdx.y;         // j block:   js  32jb..32jb+31
    const int b  = blockIdx.z;
    if (jb > (rb >> 2)) return;        // whole block above the diagonal

    __shared__ __align__(16) float sBuf[32 * 257]; // sPk (score) / sV (O phase)
    __shared__ float sP[8][256];       // [row_local][e] (8 KB)
    __shared__ float sHk[32];
    __shared__ __align__(16) float sSc[8][32];     // masked scores (1 KB)

    float (*sV)[128] = (float(*)[128])sBuf;        // alias, used after scores

    const int tid  = threadIdx.x;
    const int w    = tid >> 5;
    const int lane = tid & 31;
    const int i0 = rb * 8, j0 = jb * 32;

    // Issue V loads FIRST (4 float4/thread, coalesced); they stay in flight
    // through staging + the score phase.
    float4 vreg[4];
    {
        const float* vsrc = g_V + (b * S_ + j0) * H_;
        #pragma unroll
        for (int k = 0; k < 4; k++) {
            const int f = tid + 256 * k;         // 0..1023 float4 slots
            vreg[k] = *(const float4*)(vsrc + (f >> 5) * H_ + (f & 31) * 4);
        }
    }

    // Stage Pk rows (warp w -> rows 4w..4w+3; 8 lanes per row, coalesced)
    {
        const int row = 4 * w + (lane >> 3);
        const int fb  = lane & 7;
        const float* src = g_Pk + (b * S_ + j0 + row) * E_;
        float* dst = sBuf + row * 257;
        #pragma unroll
        for (int it = 0; it < 8; it++) {
            const int f = fb + 8 * it;          // float4 index within row
            float4 v = *(const float4*)(src + 4 * f);
            dst[4*f+0] = v.x; dst[4*f+1] = v.y;
            dst[4*f+2] = v.z; dst[4*f+3] = v.w;
        }
    }
    // Stage Pq rows (warp w -> row w, two float4 per lane, coalesced)
    {
        const float* src = g_Pq + (b * S_ + i0 + w) * E_;
        *(float4*)&sP[w][4 * lane]        = *(const float4*)(src + 4 * lane);
        *(float4*)&sP[w][128 + 4 * lane]  = *(const float4*)(src + 128 + 4 * lane);
    }
    if (tid < 32) sHk[tid] = g_entk[b * S_ + j0 + tid];
    __syncthreads();

    // --- Score phase (warp w = row i0+w, lane = j0+lane) ---
    const float hq = g_entq[b * S_ + i0 + w];
    const float hk = sHk[lane];
    const float* pkrow = sBuf + lane * 257;      // conflict-free columns

    float ac0 = 0.f, ac1 = 0.f, ac2 = 0.f, ac3 = 0.f;
    #pragma unroll 8
    for (int e = 0; e < E_; e += 4) {
        const float4 p = *(const float4*)&sP[w][e];
        const float s0 = p.x + pkrow[e + 0];
        const float s1 = p.y + pkrow[e + 1];
        const float s2 = p.z + pkrow[e + 2];
        const float s3 = p.w + pkrow[e + 3];
        ac0 = fmaf(s0, __log2f(fmaf(0.5f, s0, 1e-10f)), ac0);
        ac1 = fmaf(s1, __log2f(fmaf(0.5f, s1, 1e-10f)), ac1);
        ac2 = fmaf(s2, __log2f(fmaf(0.5f, s2, 1e-10f)), ac2);
        ac3 = fmaf(s3, __log2f(fmaf(0.5f, s3, 1e-10f)), ac3);
    }
    const float acc = (ac0 + ac1) + (ac2 + ac3);

    const int i = i0 + w, j = j0 + lane;
    const float HL = 0.34657359028f;             // 0.5 * ln(2)
    const float ms = (j <= i) ? (1.0f - HL * (hq + hk - acc)) : 0.0f;
    sSc[w][lane] = ms;

    // Per-block L1 row sum (warp butterfly; scores masked to 0 above diag)
    float rs = fabsf(ms);
    #pragma unroll
    for (int o = 16; o; o >>= 1) rs += __shfl_xor_sync(0xffffffffu, rs, o);
    if (lane == 0) g_rsp[jb][b * S_ + i] = rs;

    __syncthreads();   // all sPk reads done; safe to overwrite sBuf with V

    // Dump V registers to the aliased smem (pure STS, conflict-free)
    #pragma unroll
    for (int k = 0; k < 4; k++) {
        const int f = tid + 256 * k;
        *(float4*)&sV[f >> 5][(f & 31) * 4] = vreg[k];
    }
    __syncthreads();

    // --- Partial O phase: O_p[8 x 128] = sSc[8 x 32] @ sV[32 x 128] ---
    // thread = (row-quad = tid>>7, h = tid&127); 4 row accumulators.
    // sSc reads are warp-broadcast; sV reads conflict-free (h consecutive).
    const int h     = tid & 127;
    const int rbase = (tid >> 7) * 4;
    float acc4[4] = {};
    #pragma unroll
    for (int j4 = 0; j4 < 32; j4 += 4) {
        const float v0 = sV[j4 + 0][h];
        const float v1 = sV[j4 + 1][h];
        const float v2 = sV[j4 + 2][h];
        const float v3 = sV[j4 + 3][h];
        #pragma unroll
        for (int r = 0; r < 4; r++) {
            const float4 s = *(const float4*)&sSc[rbase + r][j4];
            acc4[r] = fmaf(s.x, v0, acc4[r]);
            acc4[r] = fmaf(s.y, v1, acc4[r]);
            acc4[r] = fmaf(s.z, v2, acc4[r]);
            acc4[r] = fmaf(s.w, v3, acc4[r]);
        }
    }
    #pragma unroll
    for (int r = 0; r < 4; r++)
        g_Op[jb][b * S_ + i0 + rbase + r][h] = acc4[r];   // coalesced in h
}

// ---------------------------------------------------------------------------
// Kernel 3c: combine partials + normalize.  thread = (row n, head h);
// sums the jb <= n>>5 (within batch) partials of O and of the L1 row sum,
// then writes out = O_sum / max(rs_sum, 1e-12).  Predication is uniform per
// 128-thread row group; 8-way unrolled -> MLP 8.  grid 512 x 256.
// ---------------------------------------------------------------------------
__global__ __launch_bounds__(256) void k3c_out(float* __restrict__ out)
{
    const int tg = blockIdx.x * 256 + threadIdx.x;  // 0..131071
    const int n  = tg >> 7;          // row 0..1023
    const int h  = tg & 127;
    const int jbmax = (n & 255) >> 5;

    float o = 0.f, rs = 0.f;
    #pragma unroll
    for (int jb = 0; jb < 8; jb++) {
        if (jb <= jbmax) {           // warp-uniform predicate
            o  += g_Op[jb][n][h];
            rs += g_rsp[jb][n];
        }
    }
    out[n * H_ + h] = o / fmaxf(rs, 1e-12f);
}

// ---------------------------------------------------------------------------
// Launch. Inputs per metadata order: x, Wv, Wq, Wk (all float32).
// ---------------------------------------------------------------------------
extern "C" void kernel_launch(void* const* d_in, const int* in_sizes, int n_in,
                              void* d_out, int out_size)
{
    const float* x  = (const float*)d_in[0];
    const float* Wv = (const float*)d_in[1];
    const float* Wq = (const float*)d_in[2];
    const float* Wk = (const float*)d_in[3];
    float* out = (float*)d_out;

    k1_gemm<<<dim3(16, 10, 2), 256>>>(x, Wq, Wk, Wv);
    k2_probs<<<384, 256>>>(x);
    k3_sv<<<dim3(32, 8, 4), 256>>>();
    k3c_out<<<512, 256>>>(out);
}

// round 16
// speedup vs baseline: 1.2008x; 1.0859x over previous
#include <cuda_runtime.h>
#include <math.h>

// Problem constants (fixed by the dataset)
#define B_ 4
#define S_ 256
#define E_ 256
#define H_ 128
#define N_ (B_ * S_)   // 1024 rows total

// Scratch (static device arrays; allocation-free per harness rules)
__device__ float g_ampq2[2][N_ * E_];   // split-K partials
__device__ float g_ampk2[2][N_ * E_];
__device__ float g_V2[2][N_ * H_];
__device__ float g_V[N_ * H_];
__device__ float g_Pq[N_ * E_];   // row-major, query side
__device__ float g_Pk[N_ * E_];   // row-major, key side
__device__ float g_entq[N_];      // sum_e P * lg2(P + 1e-10)
__device__ float g_entk[N_];
__device__ float g_O[N_ * H_];    // atomically-accumulated output numerator
__device__ float g_rs[N_];        // atomically-accumulated L1 row sums

// ---------------------------------------------------------------------------
// Kernel 1: split-K double-buffered GEMM, k-chunk 16 -> 17.4 KB smem ->
// 2 CTAs/SM (16 warps; the R9 double-buffer at 34.8 KB silently dropped k1
// to 1 CTA/SM).  Same proven 64x64 tile / 4x4 micro / 16 FFMA per 2 LDS.128.
// C[1024, 640] = x[1024,256] @ [Wq;Wk;Wv]^T, z = K-half.  Grid 16x10x2.
// ---------------------------------------------------------------------------
__global__ __launch_bounds__(256) void k1_gemm(
    const float* __restrict__ x,
    const float* __restrict__ Wq,
    const float* __restrict__ Wk,
    const float* __restrict__ Wv)
{
    __shared__ float As[2][16][68];  // [buf][k][m], pad keeps float4 alignment
    __shared__ float Bs[2][16][68];  // [buf][k][f]

    const int m0 = blockIdx.x * 64;       // row tile (0..15)
    const int f0 = blockIdx.y * 64;       // f tile (0..9) over concat 640
    const int z  = blockIdx.z;            // K half
    const int kbase = z * 128;

    const float* Wp; float* outp; int fo, ostride;
    if (f0 < 256)      { Wp = Wq; fo = f0;       outp = g_ampq2[z]; ostride = E_; }
    else if (f0 < 512) { Wp = Wk; fo = f0 - 256; outp = g_ampk2[z]; ostride = E_; }
    else               { Wp = Wv; fo = f0 - 512; outp = g_V2[z];    ostride = H_; }

    const int tid  = threadIdx.x;
    const int tx   = tid & 15;            // f micro
    const int ty   = tid >> 4;            // m micro
    const int lrow = tid >> 2;            // 0..63 loader row
    const int lk   = (tid & 3) * 4;       // 0,4,8,12 loader k base

    const float* xg = x  + (m0 + lrow) * E_ + kbase + lk;
    const float* wg = Wp + (fo + lrow) * E_ + kbase + lk;

    float acc[4][4] = {};

    float4 a0 = *(const float4*)(xg);
    float4 b0 = *(const float4*)(wg);
    {
        As[0][lk+0][lrow] = a0.x; As[0][lk+1][lrow] = a0.y;
        As[0][lk+2][lrow] = a0.z; As[0][lk+3][lrow] = a0.w;
        Bs[0][lk+0][lrow] = b0.x; Bs[0][lk+1][lrow] = b0.y;
        Bs[0][lk+2][lrow] = b0.z; Bs[0][lk+3][lrow] = b0.w;
    }
    __syncthreads();

    #pragma unroll
    for (int c = 0; c < 8; c++) {
        const int buf = c & 1;
        if (c < 7) {                      // prefetch next chunk BEFORE compute
            const int k0 = (c + 1) * 16;
            a0 = *(const float4*)(xg + k0);
            b0 = *(const float4*)(wg + k0);
        }

        #pragma unroll
        for (int kk = 0; kk < 16; kk++) {
            float4 av = *(const float4*)&As[buf][kk][ty * 4];
            float4 bv = *(const float4*)&Bs[buf][kk][tx * 4];
            acc[0][0] = fmaf(av.x, bv.x, acc[0][0]);
            acc[0][1] = fmaf(av.x, bv.y, acc[0][1]);
            acc[0][2] = fmaf(av.x, bv.z, acc[0][2]);
            acc[0][3] = fmaf(av.x, bv.w, acc[0][3]);
            acc[1][0] = fmaf(av.y, bv.x, acc[1][0]);
            acc[1][1] = fmaf(av.y, bv.y, acc[1][1]);
            acc[1][2] = fmaf(av.y, bv.z, acc[1][2]);
            acc[1][3] = fmaf(av.y, bv.w, acc[1][3]);
            acc[2][0] = fmaf(av.z, bv.x, acc[2][0]);
            acc[2][1] = fmaf(av.z, bv.y, acc[2][1]);
            acc[2][2] = fmaf(av.z, bv.z, acc[2][2]);
            acc[2][3] = fmaf(av.z, bv.w, acc[2][3]);
            acc[3][0] = fmaf(av.w, bv.x, acc[3][0]);
            acc[3][1] = fmaf(av.w, bv.y, acc[3][1]);
            acc[3][2] = fmaf(av.w, bv.z, acc[3][2]);
            acc[3][3] = fmaf(av.w, bv.w, acc[3][3]);
        }

        if (c < 7) {                      // stage next chunk into other buffer
            const int nb = buf ^ 1;
            As[nb][lk+0][lrow] = a0.x; As[nb][lk+1][lrow] = a0.y;
            As[nb][lk+2][lrow] = a0.z; As[nb][lk+3][lrow] = a0.w;
            Bs[nb][lk+0][lrow] = b0.x; Bs[nb][lk+1][lrow] = b0.y;
            Bs[nb][lk+2][lrow] = b0.z; Bs[nb][lk+3][lrow] = b0.w;
            __syncthreads();
        }
    }

    #pragma unroll
    for (int i = 0; i < 4; i++) {
        const int row = m0 + ty * 4 + i;
        float4 v = make_float4(acc[i][0], acc[i][1], acc[i][2], acc[i][3]);
        *(float4*)&outp[row * ostride + fo + tx * 4] = v;
    }
}

// ---------------------------------------------------------------------------
// Kernel 2: warp-per-row split-K combine + probs + entropy, plus a 4th
// region that ZEROES the atomic accumulators g_O / g_rs (inside the graph,
// so every replay starts clean).  Regions 0/1 (q/k): amp = part0+part1,
// P = amp^2/(ssq+EPS*d^2), ent = sum P*lg2(P+EPS).  Region 2: V = V0+V1.
// Region 3: g_O row + g_rs zero.  grid 512 x 256.
// ---------------------------------------------------------------------------
__global__ __launch_bounds__(256) void k2_probs(const float* __restrict__ x)
{
    const int w    = threadIdx.x >> 5;
    const int lane = threadIdx.x & 31;
    const int slot = blockIdx.x * 8 + w;       // 0..4095
    const int regn = slot >> 10;               // 0=q, 1=k, 2=V-combine, 3=zero
    const int n    = slot & 1023;

    if (regn == 3) {                           // zero accumulators for this row
        ((float4*)&g_O[n * H_])[lane] = make_float4(0.f, 0.f, 0.f, 0.f);
        if (lane == 0) g_rs[n] = 0.f;
        return;
    }
    if (regn == 2) {
        const float4* v0 = (const float4*)&g_V2[0][n * H_];
        const float4* v1 = (const float4*)&g_V2[1][n * H_];
        float4*       vo = (float4*)&g_V[n * H_];
        const float4 a = v0[lane], b = v1[lane];
        vo[lane] = make_float4(a.x + b.x, a.y + b.y, a.z + b.z, a.w + b.w);
        return;
    }

    const float* a0 = (regn ? g_ampk2[0] : g_ampq2[0]) + n * E_;
    const float* a1 = (regn ? g_ampk2[1] : g_ampq2[1]) + n * E_;
    float*     Pout = (regn ? g_Pk       : g_Pq)       + n * E_;
    const float* xr = x + n * E_;

    float a[8];
    float ssa = 0.f, ssx = 0.f;
    #pragma unroll
    for (int m = 0; m < 8; m++) {
        a[m] = a0[lane + 32 * m] + a1[lane + 32 * m];
        float xv = xr[lane + 32 * m];
        ssa = fmaf(a[m], a[m], ssa);
        ssx = fmaf(xv, xv, ssx);
    }
    #pragma unroll
    for (int o = 16; o; o >>= 1) {
        ssa += __shfl_xor_sync(0xffffffffu, ssa, o);
        ssx += __shfl_xor_sync(0xffffffffu, ssx, o);
    }
    const float d   = sqrtf(ssx) + 1e-12f;
    const float inv = 1.0f / (ssa + 1e-10f * d * d);

    float ent = 0.f;
    #pragma unroll
    for (int m = 0; m < 8; m++) {
        const float P = a[m] * a[m] * inv;
        ent = fmaf(P, __log2f(P + 1e-10f), ent);
        Pout[lane + 32 * m] = P;
    }
    #pragma unroll
    for (int o = 16; o; o >>= 1)
        ent += __shfl_xor_sync(0xffffffffu, ent, o);
    if (lane == 0) (regn ? g_entk : g_entq)[n] = ent;
}

// ---------------------------------------------------------------------------
// Kernel 3 (fused): JS scores + masked score-block @ V-block, accumulating
// DIRECTLY into g_O / g_rs via atomicAdd (RED, no return wait) -- this
// removes the 4 MB partial-buffer round-trip and most of the old combine
// kernel.  sPk[32][257] (conflict-free columns) is time-multiplexed with
// the V block; V is LDG'd into registers at kernel entry (in flight through
// staging + the MUFU-bound score phase).  Static smem 41.25 KB.
// CTA = (8-row block, 32-j block, batch); grid (32, 8, 4).
// ---------------------------------------------------------------------------
__global__ __launch_bounds__(256) void k3_sv()
{
    const int rb = blockIdx.x;         // row block: rows 8rb..8rb+7
    const int jb = blockIdx.y;         // j block:   js  32jb..32jb+31
    const int b  = blockIdx.z;
    if (jb > (rb >> 2)) return;        // whole block above the diagonal

    __shared__ __align__(16) float sBuf[32 * 257]; // sPk (score) / sV (O phase)
    __shared__ float sP[8][256];       // [row_local][e] (8 KB)
    __shared__ float sHk[32];
    __shared__ __align__(16) float sSc[8][32];     // masked scores (1 KB)

    float (*sV)[128] = (float(*)[128])sBuf;        // alias, used after scores

    const int tid  = threadIdx.x;
    const int w    = tid >> 5;
    const int lane = tid & 31;
    const int i0 = rb * 8, j0 = jb * 32;

    // Issue V loads FIRST (4 float4/thread, coalesced); in flight through
    // staging + score phase.
    float4 vreg[4];
    {
        const float* vsrc = g_V + (b * S_ + j0) * H_;
        #pragma unroll
        for (int k = 0; k < 4; k++) {
            const int f = tid + 256 * k;         // 0..1023 float4 slots
            vreg[k] = *(const float4*)(vsrc + (f >> 5) * H_ + (f & 31) * 4);
        }
    }

    // Stage Pk rows (warp w -> rows 4w..4w+3; 8 lanes per row, coalesced)
    {
        const int row = 4 * w + (lane >> 3);
        const int fb  = lane & 7;
        const float* src = g_Pk + (b * S_ + j0 + row) * E_;
        float* dst = sBuf + row * 257;
        #pragma unroll
        for (int it = 0; it < 8; it++) {
            const int f = fb + 8 * it;          // float4 index within row
            float4 v = *(const float4*)(src + 4 * f);
            dst[4*f+0] = v.x; dst[4*f+1] = v.y;
            dst[4*f+2] = v.z; dst[4*f+3] = v.w;
        }
    }
    // Stage Pq rows (warp w -> row w, two float4 per lane, coalesced)
    {
        const float* src = g_Pq + (b * S_ + i0 + w) * E_;
        *(float4*)&sP[w][4 * lane]        = *(const float4*)(src + 4 * lane);
        *(float4*)&sP[w][128 + 4 * lane]  = *(const float4*)(src + 128 + 4 * lane);
    }
    if (tid < 32) sHk[tid] = g_entk[b * S_ + j0 + tid];
    __syncthreads();

    // --- Score phase (warp w = row i0+w, lane = j0+lane) ---
    const float hq = g_entq[b * S_ + i0 + w];
    const float hk = sHk[lane];
    const float* pkrow = sBuf + lane * 257;      // conflict-free columns

    float ac0 = 0.f, ac1 = 0.f, ac2 = 0.f, ac3 = 0.f;
    #pragma unroll 8
    for (int e = 0; e < E_; e += 4) {
        const float4 p = *(const float4*)&sP[w][e];
        const float s0 = p.x + pkrow[e + 0];
        const float s1 = p.y + pkrow[e + 1];
        const float s2 = p.z + pkrow[e + 2];
        const float s3 = p.w + pkrow[e + 3];
        ac0 = fmaf(s0, __log2f(fmaf(0.5f, s0, 1e-10f)), ac0);
        ac1 = fmaf(s1, __log2f(fmaf(0.5f, s1, 1e-10f)), ac1);
        ac2 = fmaf(s2, __log2f(fmaf(0.5f, s2, 1e-10f)), ac2);
        ac3 = fmaf(s3, __log2f(fmaf(0.5f, s3, 1e-10f)), ac3);
    }
    const float acc = (ac0 + ac1) + (ac2 + ac3);

    const int i = i0 + w, j = j0 + lane;
    const float HL = 0.34657359028f;             // 0.5 * ln(2)
    const float ms = (j <= i) ? (1.0f - HL * (hq + hk - acc)) : 0.0f;
    sSc[w][lane] = ms;

    // Per-block L1 row sum -> atomic accumulate (scores masked to 0)
    float rs = fabsf(ms);
    #pragma unroll
    for (int o = 16; o; o >>= 1) rs += __shfl_xor_sync(0xffffffffu, rs, o);
    if (lane == 0) atomicAdd(&g_rs[b * S_ + i], rs);

    __syncthreads();   // all sPk reads done; safe to overwrite sBuf with V

    // Dump V registers to the aliased smem (pure STS, conflict-free)
    #pragma unroll
    for (int k = 0; k < 4; k++) {
        const int f = tid + 256 * k;
        *(float4*)&sV[f >> 5][(f & 31) * 4] = vreg[k];
    }
    __syncthreads();

    // --- Partial O phase: O_p[8 x 128] = sSc[8 x 32] @ sV[32 x 128],
    // reduced straight into g_O via RED.  thread = (row-quad, h).
    const int h     = tid & 127;
    const int rbase = (tid >> 7) * 4;
    float acc4[4] = {};
    #pragma unroll
    for (int j4 = 0; j4 < 32; j4 += 4) {
        const float v0 = sV[j4 + 0][h];
        const float v1 = sV[j4 + 1][h];
        const float v2 = sV[j4 + 2][h];
        const float v3 = sV[j4 + 3][h];
        #pragma unroll
        for (int r = 0; r < 4; r++) {
            const float4 s = *(const float4*)&sSc[rbase + r][j4];
            acc4[r] = fmaf(s.x, v0, acc4[r]);
            acc4[r] = fmaf(s.y, v1, acc4[r]);
            acc4[r] = fmaf(s.z, v2, acc4[r]);
            acc4[r] = fmaf(s.w, v3, acc4[r]);
        }
    }
    #pragma unroll
    for (int r = 0; r < 4; r++)
        atomicAdd(&g_O[(b * S_ + i0 + rbase + r) * H_ + h], acc4[r]);
}

// ---------------------------------------------------------------------------
// Kernel 3c: pure normalize.  out[n,h] = g_O[n,h] / max(g_rs[n], 1e-12).
// grid 512 x 256 (thread = (row n, head h)); coalesced, ~1 MB of traffic.
// ---------------------------------------------------------------------------
__global__ __launch_bounds__(256) void k3c_out(float* __restrict__ out)
{
    const int tg = blockIdx.x * 256 + threadIdx.x;  // 0..131071
    const int n  = tg >> 7;          // row 0..1023
    const int h  = tg & 127;
    out[n * H_ + h] = g_O[n * H_ + h] / fmaxf(g_rs[n], 1e-12f);
}

// ---------------------------------------------------------------------------
// Launch. Inputs per metadata order: x, Wv, Wq, Wk (all float32).
// ---------------------------------------------------------------------------
extern "C" void kernel_launch(void* const* d_in, const int* in_sizes, int n_in,
                              void* d_out, int out_size)
{
    const float* x  = (const float*)d_in[0];
    const float* Wv = (const float*)d_in[1];
    const float* Wq = (const float*)d_in[2];
    const float* Wk = (const float*)d_in[3];
    float* out = (float*)d_out;

    k1_gemm<<<dim3(16, 10, 2), 256>>>(x, Wq, Wk, Wv);
    k2_probs<<<512, 256>>>(x);
    k3_sv<<<dim3(32, 8, 4), 256>>>();
    k3c_out<<<512, 256>>>(out);
}